// round 9
// baseline (speedup 1.0000x reference)
#include <cuda_runtime.h>
#include <cuda_fp16.h>
#include <cstdint>
#include <math.h>

// ---------------- fixed problem shapes ----------------
#define N_TOK   32760          // 21 * 1560
#define DIM     1536
#define NHEADS  12
#define HD      128
#define S_SP    1560
#define N_T     21
#define ENC     768
#define NA      32
#define KV_ROWS 672
#define PKDIM   384            // NHEADS * NA
#define LOG2_10000 13.287712379549449f

// ---------------- scratch ----------------
__device__ __half g_xh[N_TOK * DIM];          // fp16 x
__device__ __half g_qh[N_TOK * DIM];          // fp16 RoPE'd q
__device__ __half g_qwh[DIM * DIM];           // fp16 q_w
__device__ __half g_ehsh[KV_ROWS * ENC];      // fp16 encoder states
__device__ __half g_kvwh[2 * DIM * ENC];      // fp16 kv_w
__device__ float  g_kv[KV_ROWS * 2 * DIM];    // kv projection (fp32)
__device__ float  g_k[KV_ROWS * DIM];
__device__ float  g_v[KV_ROWS * DIM];
__device__ __half g_probsh[N_TOK * PKDIM];    // softmax probs [t*S+s][h*32+a]
__device__ __half g_w2h[N_T * DIM * PKDIM];   // W2^T [b][c][h*32+a]
__device__ float  g_pos[N_TOK];
__device__ float  g_mm[4];

// ---------------- helpers ----------------
__device__ __forceinline__ uint32_t smem_u32(const void* p) {
    uint32_t r;
    asm("{.reg .u64 t; cvta.to.shared.u64 t, %1; cvt.u32.u64 %0, t;}" : "=r"(r) : "l"(p));
    return r;
}

#define LDSM4(r0, r1, r2, r3, addr)                                            \
    asm volatile("ldmatrix.sync.aligned.m8n8.x4.shared.b16 {%0,%1,%2,%3}, [%4];" \
                 : "=r"(r0), "=r"(r1), "=r"(r2), "=r"(r3) : "r"(addr))

#define MMA_F16(d, a, b0, b1)                                                  \
    asm volatile("mma.sync.aligned.m16n8k16.row.col.f32.f16.f16.f32 "           \
                 "{%0,%1,%2,%3},{%4,%5,%6,%7},{%8,%9},{%0,%1,%2,%3};"          \
                 : "+f"(d[0]), "+f"(d[1]), "+f"(d[2]), "+f"(d[3])              \
                 : "r"(a[0]), "r"(a[1]), "r"(a[2]), "r"(a[3]), "r"(b0), "r"(b1))

// ---------------- fp32 -> fp16 conversion ----------------
__global__ void cvt_half_kernel(const float* __restrict__ in, __half* __restrict__ out, int n4) {
    int i = blockIdx.x * blockDim.x + threadIdx.x;
    if (i >= n4) return;
    float4 v = ((const float4*)in)[i];
    __half2 h0 = __floats2half2_rn(v.x, v.y);
    __half2 h1 = __floats2half2_rn(v.z, v.w);
    uint2 pk;
    pk.x = *(uint32_t*)&h0;
    pk.y = *(uint32_t*)&h1;
    ((uint2*)out)[i] = pk;
}

// ---------------- min/max of attn-map rows (single CTA, float4) ----------------
__global__ void minmax_kernel(const float* __restrict__ m) {
    __shared__ float s0[512], s1[512], s2[512], s3[512];
    int tid = threadIdx.x;
    float mn0 = 1e30f, mx0 = -1e30f, mn1 = 1e30f, mx1 = -1e30f;
    // N_TOK = 32760 = 8190 float4
    const float4* m0v = (const float4*)m;
    const float4* m1v = (const float4*)(m + N_TOK);
    for (int i = tid; i < N_TOK / 4; i += 512) {
        float4 v0 = m0v[i], v1 = m1v[i];
        mn0 = fminf(mn0, fminf(fminf(v0.x, v0.y), fminf(v0.z, v0.w)));
        mx0 = fmaxf(mx0, fmaxf(fmaxf(v0.x, v0.y), fmaxf(v0.z, v0.w)));
        mn1 = fminf(mn1, fminf(fminf(v1.x, v1.y), fminf(v1.z, v1.w)));
        mx1 = fmaxf(mx1, fmaxf(fmaxf(v1.x, v1.y), fmaxf(v1.z, v1.w)));
    }
    s0[tid] = mn0; s1[tid] = mx0; s2[tid] = mn1; s3[tid] = mx1;
    __syncthreads();
    for (int off = 256; off > 0; off >>= 1) {
        if (tid < off) {
            s0[tid] = fminf(s0[tid], s0[tid + off]);
            s1[tid] = fmaxf(s1[tid], s1[tid + off]);
            s2[tid] = fminf(s2[tid], s2[tid + off]);
            s3[tid] = fmaxf(s3[tid], s3[tid + off]);
        }
        __syncthreads();
    }
    if (tid == 0) { g_mm[0] = s0[0]; g_mm[1] = s1[0]; g_mm[2] = s2[0]; g_mm[3] = s3[0]; }
}

// ---------------- routing positions ----------------
__global__ void pos_kernel(const float* __restrict__ m) {
    int n = blockIdx.x * blockDim.x + threadIdx.x;
    if (n >= N_TOK) return;
    float m0 = m[n], m1 = m[N_TOK + n];
    float r;
    if (m0 >= m1) r = (m0 - g_mm[0]) / (g_mm[1] - g_mm[0] + 1e-8f) * 4.0f;
    else          r = (m1 - g_mm[2]) / (g_mm[3] - g_mm[2] + 1e-8f) * 4.0f + 20.0f;
    g_pos[n] = r;
}

// ======== fp16 mma GEMM: C[M,N] = A[M,K] @ B[N,K]^T + bias (+RoPE, batched) ========
#define KCHUNK  64
#define STAGES  4
#define SM_ASZ  16384
#define SM_BSZ  32768
#define SM_TOT  (STAGES * (SM_ASZ + SM_BSZ))   // 196608

__device__ __forceinline__ void fill_stage(
    const __half* __restrict__ A, const __half* __restrict__ B, int M, int K,
    int row0, int col0, int kt, uint32_t sA, uint32_t sB, int tid)
{
#pragma unroll
    for (int g = 0; g < 4; g++) {                // A: 128 rows x 8 chunks of 16B
        int ga = tid + g * 256;
        int row = ga >> 3, ch = ga & 7;
        uint32_t dst = sA + (uint32_t)row * 128u + (((uint32_t)ch * 16u) ^ (((uint32_t)row & 7u) << 4));
        const __half* src = A + (size_t)(row0 + row) * K + kt * KCHUNK + ch * 8;
        int sz = (row0 + row < M) ? 16 : 0;
        asm volatile("cp.async.cg.shared.global [%0], [%1], 16, %2;" :: "r"(dst), "l"(src), "r"(sz));
    }
#pragma unroll
    for (int g = 0; g < 8; g++) {                // B: 256 rows x 8 chunks of 16B
        int gb = tid + g * 256;
        int row = gb >> 3, ch = gb & 7;
        uint32_t dst = sB + (uint32_t)row * 128u + (((uint32_t)ch * 16u) ^ (((uint32_t)row & 7u) << 4));
        const __half* src = B + (size_t)(col0 + row) * K + kt * KCHUNK + ch * 8;
        asm volatile("cp.async.cg.shared.global [%0], [%1], 16;" :: "r"(dst), "l"(src));
    }
    asm volatile("cp.async.commit_group;");
}

template <bool FUSE_ROPE, bool HALF_OUT>
__global__ void __launch_bounds__(256, 1) gemm_f16(
    const __half* __restrict__ A, const __half* __restrict__ B,
    const float* __restrict__ bias, void* __restrict__ Cv,
    int M, int N, int K, size_t strA, size_t strB, size_t strC)
{
    extern __shared__ float smem[];
    const int tid  = threadIdx.x;
    const int lane = tid & 31, warp = tid >> 5;
    const int wm = warp >> 2, wn = warp & 3;
    const int row0 = blockIdx.y * 128, col0 = blockIdx.x * 256;

    A += (size_t)blockIdx.z * strA;
    B += (size_t)blockIdx.z * strB;

    const uint32_t sA = smem_u32(smem);
    const uint32_t sB = sA + STAGES * SM_ASZ;
    const int ktiles = K / KCHUNK;

    fill_stage(A, B, M, K, row0, col0, 0, sA, sB, tid);
    fill_stage(A, B, M, K, row0, col0, 1, sA + SM_ASZ, sB + SM_BSZ, tid);
    fill_stage(A, B, M, K, row0, col0, 2, sA + 2 * SM_ASZ, sB + 2 * SM_BSZ, tid);

    float acc[4][8][4];
#pragma unroll
    for (int i = 0; i < 4; i++)
#pragma unroll
        for (int j = 0; j < 8; j++)
#pragma unroll
            for (int k = 0; k < 4; k++) acc[i][j][k] = 0.0f;

    const int aRow = wm * 64 + ((lane >> 3) & 1) * 8 + (lane & 7);
    const int bRow = wn * 64 + ((lane >> 3) & 1) * 8 + (lane & 7);
    const uint32_t colSel = ((lane >> 4) & 1) * 16;
    const uint32_t xorv = ((uint32_t)lane & 7u) << 4;

    for (int it = 0; it < ktiles; it++) {
        if (it < ktiles - 2)       asm volatile("cp.async.wait_group 2;" ::: "memory");
        else if (it == ktiles - 2) asm volatile("cp.async.wait_group 1;" ::: "memory");
        else                       asm volatile("cp.async.wait_group 0;" ::: "memory");
        __syncthreads();
        const int st = it & 3;
        const uint32_t bA = sA + st * SM_ASZ;
        const uint32_t bB = sB + st * SM_BSZ;
#pragma unroll
        for (int ks = 0; ks < 4; ks++) {
            uint32_t a[4][4], bb[4][4];
            const uint32_t cb = ((uint32_t)(ks * 32) + colSel) ^ xorv;
#pragma unroll
            for (int mf = 0; mf < 4; mf++) {
                uint32_t ad = bA + (uint32_t)(aRow + mf * 16) * 128 + cb;
                LDSM4(a[mf][0], a[mf][1], a[mf][2], a[mf][3], ad);
            }
#pragma unroll
            for (int ng = 0; ng < 4; ng++) {
                uint32_t bd = bB + (uint32_t)(bRow + ng * 16) * 128 + cb;
                LDSM4(bb[ng][0], bb[ng][1], bb[ng][2], bb[ng][3], bd);
            }
#pragma unroll
            for (int mf = 0; mf < 4; mf++)
#pragma unroll
                for (int nf = 0; nf < 8; nf++) {
                    const int ng = nf >> 1, lo = nf & 1;
                    MMA_F16(acc[mf][nf], a[mf], bb[ng][lo], bb[ng][2 + lo]);
                }
        }
        if (it + 3 < ktiles) {
            const int r = it + 3;
            fill_stage(A, B, M, K, row0, col0, r,
                       sA + (r & 3) * SM_ASZ, sB + (r & 3) * SM_BSZ, tid);
        }
    }

    // epilogue: c0,c1 at (row=lane>>2, col=2*(lane&3)); c2,c3 at row+8
#pragma unroll
    for (int mf = 0; mf < 4; mf++) {
        const int r0 = row0 + wm * 64 + mf * 16 + (lane >> 2);
        const int r8 = r0 + 8;
        float pos0 = 0.f, pos8 = 0.f;
        if (FUSE_ROPE) {
            pos0 = g_pos[(r0 < M) ? r0 : 0];
            pos8 = g_pos[(r8 < M) ? r8 : 0];
        }
#pragma unroll
        for (int nf = 0; nf < 8; nf++) {
            const int c = col0 + wn * 64 + nf * 8 + (lane & 3) * 2;
            const float2 bv = *(const float2*)(bias + c);
            float o0 = acc[mf][nf][0] + bv.x;
            float o1 = acc[mf][nf][1] + bv.y;
            float o2 = acc[mf][nf][2] + bv.x;
            float o3 = acc[mf][nf][3] + bv.y;
            if (FUSE_ROPE) {
                const int i = (c & 127) >> 1;
                const float fr = exp2f(-(float)i * (LOG2_10000 / 64.0f));
                float sn, cs;
                sincosf(pos0 * fr, &sn, &cs);
                float t0 = o0 * cs - o1 * sn;
                o1 = o1 * cs + o0 * sn; o0 = t0;
                sincosf(pos8 * fr, &sn, &cs);
                float t2 = o2 * cs - o3 * sn;
                o3 = o3 * cs + o2 * sn; o2 = t2;
            }
            if (HALF_OUT) {
                __half* C = (__half*)Cv + (size_t)blockIdx.z * strC;
                if (r0 < M) *(__half2*)(C + (size_t)r0 * N + c) = __floats2half2_rn(o0, o1);
                if (r8 < M) *(__half2*)(C + (size_t)r8 * N + c) = __floats2half2_rn(o2, o3);
            } else {
                float* C = (float*)Cv + (size_t)blockIdx.z * strC;
                if (r0 < M) *(float2*)(C + (size_t)r0 * N + c) = make_float2(o0, o1);
                if (r8 < M) *(float2*)(C + (size_t)r8 * N + c) = make_float2(o2, o3);
            }
        }
    }
}

// ---------------- split kv -> k (bucket-centre RoPE) and v ----------------
__global__ void rope_k_split_kernel() {
    int idx = blockIdx.x * blockDim.x + threadIdx.x;
    if (idx >= KV_ROWS * (DIM / 2)) return;
    int r = idx / (DIM / 2);
    int p = idx - r * (DIM / 2);
    int a = r & 31;
    float pos = (a < 16) ? 2.0f : 22.0f;
    int i = p & 63;
    float fr = exp2f(-(float)i * (LOG2_10000 / 64.0f));
    float th = pos * fr;
    float s, c;
    sincosf(th, &s, &c);
    const float* kvr = g_kv + (size_t)r * (2 * DIM);
    float ka = kvr[2 * p], kb = kvr[2 * p + 1];
    size_t o = (size_t)r * DIM + 2 * p;
    g_k[o]     = ka * c - kb * s;
    g_k[o + 1] = kb * c + ka * s;
    g_v[o]     = kvr[DIM + 2 * p];
    g_v[o + 1] = kvr[DIM + 2 * p + 1];
}

// ---------------- attention probs: scores + softmax only (KV len 32) ----------
__global__ void __launch_bounds__(256) attn_probs_kernel() {
    const int h = blockIdx.x;
    const int t = blockIdx.y;
    __shared__ float ks[32][129];
    __shared__ __half qs[8][128];

    const int tid = threadIdx.x;
    for (int i = tid; i < 32 * 128; i += 256) {
        int a = i >> 7, d = i & 127;
        ks[a][d] = g_k[(size_t)(t * 32 + a) * DIM + h * HD + d];
    }
    __syncthreads();

    const int w = tid >> 5, l = tid & 31;

    for (int s = w; s < S_SP; s += 8) {
        size_t qoff = (size_t)(t * S_SP + s) * DIM + h * HD;
        ((uint2*)&qs[w][0])[l] = *(const uint2*)(g_qh + qoff + 4 * l);
        __syncwarp();

        float acc = 0.0f;
        const __half2* q2 = (const __half2*)&qs[w][0];
        const float* kr = &ks[l][0];
#pragma unroll
        for (int j = 0; j < 64; j++) {
            float2 qf = __half22float2(q2[j]);
            acc += qf.x * kr[2 * j] + qf.y * kr[2 * j + 1];
        }
        acc *= 0.08838834764831845f;

        float mx = acc;
#pragma unroll
        for (int o = 16; o > 0; o >>= 1) mx = fmaxf(mx, __shfl_xor_sync(0xFFFFFFFFu, mx, o));
        float e = __expf(acc - mx);
        float sum = e;
#pragma unroll
        for (int o = 16; o > 0; o >>= 1) sum += __shfl_xor_sync(0xFFFFFFFFu, sum, o);
        float p = e / sum;

        g_probsh[(size_t)(t * S_SP + s) * PKDIM + h * NA + l] = __float2half_rn(p);
        __syncwarp();
    }
}

// ---------------- W2[b,h] = V[b,h] @ proj_slice_h  (rank-32 fold of proj) -----
__global__ void __launch_bounds__(128) w2_kernel(const float* __restrict__ pw) {
    const int ct = blockIdx.x;
    const int h  = blockIdx.y;
    const int b  = blockIdx.z;
    __shared__ float Vs[32][128];

    const int tid = threadIdx.x;
    for (int i = tid; i < 32 * 128; i += 128) {
        int a = i >> 7, d = i & 127;
        Vs[a][d] = g_v[(size_t)(b * 32 + a) * DIM + h * HD + d];
    }
    __syncthreads();

    const int c = ct * 128 + tid;
    float acc[32];
#pragma unroll
    for (int a = 0; a < 32; a++) acc[a] = 0.0f;

    const float* pwr = pw + (size_t)c * DIM + h * HD;
#pragma unroll
    for (int chunk = 0; chunk < 4; chunk++) {
        float pr[32];
#pragma unroll
        for (int j = 0; j < 8; j++) {
            float4 v4 = *(const float4*)(pwr + chunk * 32 + j * 4);
            pr[j * 4 + 0] = v4.x; pr[j * 4 + 1] = v4.y;
            pr[j * 4 + 2] = v4.z; pr[j * 4 + 3] = v4.w;
        }
#pragma unroll
        for (int a = 0; a < 32; a++) {
#pragma unroll
            for (int j = 0; j < 32; j++)
                acc[a] += pr[j] * Vs[a][chunk * 32 + j];
        }
    }

    __half* dst = g_w2h + (size_t)b * DIM * PKDIM + (size_t)c * PKDIM + h * NA;
#pragma unroll
    for (int a = 0; a < 32; a += 2)
        *(__half2*)(dst + a) = __floats2half2_rn(acc[a], acc[a + 1]);
}

// ---------------- launch (fork-join capture; falls back to single stream) ----
extern "C" void kernel_launch(void* const* d_in, const int* in_sizes, int n_in,
                              void* d_out, int out_size)
{
    const float* x    = (const float*)d_in[0];
    const float* ehs  = (const float*)d_in[1];
    const float* amap = (const float*)d_in[2];
    const float* q_w  = (const float*)d_in[3];
    const float* q_b  = (const float*)d_in[4];
    const float* kv_w = (const float*)d_in[5];
    const float* kv_b = (const float*)d_in[6];
    const float* p_w  = (const float*)d_in[7];
    const float* p_b  = (const float*)d_in[8];
    float* out = (float*)d_out;

    __half *xh, *qh, *qwh, *ehsh, *kvwh, *probsh, *w2h;
    float *kv;
    cudaGetSymbolAddress((void**)&xh,     g_xh);
    cudaGetSymbolAddress((void**)&qh,     g_qh);
    cudaGetSymbolAddress((void**)&qwh,    g_qwh);
    cudaGetSymbolAddress((void**)&ehsh,   g_ehsh);
    cudaGetSymbolAddress((void**)&kvwh,   g_kvwh);
    cudaGetSymbolAddress((void**)&probsh, g_probsh);
    cudaGetSymbolAddress((void**)&w2h,    g_w2h);
    cudaGetSymbolAddress((void**)&kv,     g_kv);

    cudaFuncSetAttribute((const void*)gemm_f16<true, true>,
                         cudaFuncAttributeMaxDynamicSharedMemorySize, SM_TOT);
    cudaFuncSetAttribute((const void*)gemm_f16<false, false>,
                         cudaFuncAttributeMaxDynamicSharedMemorySize, SM_TOT);

    // one-time stream/event setup (host resources only; created on the first
    // call — the correctness run — so graph capture sees no new allocations)
    static bool init_done = false;
    static bool have_side = false;
    static cudaStream_t s1 = nullptr;
    static cudaEvent_t evRoot = nullptr, evK = nullptr, evSide = nullptr;
    if (!init_done) {
        init_done = true;
        if (cudaStreamCreateWithFlags(&s1, cudaStreamNonBlocking) == cudaSuccess &&
            cudaEventCreateWithFlags(&evRoot, cudaEventDisableTiming) == cudaSuccess &&
            cudaEventCreateWithFlags(&evK,    cudaEventDisableTiming) == cudaSuccess &&
            cudaEventCreateWithFlags(&evSide, cudaEventDisableTiming) == cudaSuccess) {
            have_side = true;
        }
    }
    cudaStream_t sside = have_side ? s1 : (cudaStream_t)0;

    // fork: side branch (kv chain) runs concurrently with the q critical path
    if (have_side) {
        cudaEventRecord(evRoot, 0);
        cudaStreamWaitEvent(sside, evRoot, 0);
    }

    // ---- side branch: encoder KV chain -> W2 fold ----
    cvt_half_kernel<<<(KV_ROWS * ENC / 4 + 255) / 256, 256, 0, sside>>>(ehs, ehsh, KV_ROWS * ENC / 4);
    cvt_half_kernel<<<(2 * DIM * ENC / 4 + 255) / 256, 256, 0, sside>>>(kv_w, kvwh, 2 * DIM * ENC / 4);
    gemm_f16<false, false><<<dim3((2 * DIM) / 256, (KV_ROWS + 127) / 128, 1), 256, SM_TOT, sside>>>(
        ehsh, kvwh, kv_b, kv, KV_ROWS, 2 * DIM, ENC, 0, 0, 0);
    rope_k_split_kernel<<<(KV_ROWS * (DIM / 2) + 255) / 256, 256, 0, sside>>>();
    if (have_side) cudaEventRecord(evK, sside);        // k ready (for attn)
    w2_kernel<<<dim3(DIM / 128, NHEADS, N_T), 128, 0, sside>>>(p_w);
    if (have_side) cudaEventRecord(evSide, sside);     // W2 ready (for final GEMM)

    // ---- critical path (default stream): routing -> q GEMM -> attn -> final ----
    minmax_kernel<<<1, 512>>>(amap);
    pos_kernel<<<(N_TOK + 255) / 256, 256>>>(amap);
    cvt_half_kernel<<<(DIM * DIM / 4 + 255) / 256, 256>>>(q_w, qwh, DIM * DIM / 4);
    cvt_half_kernel<<<(N_TOK * DIM / 4 + 255) / 256, 256>>>(x, xh, N_TOK * DIM / 4);

    gemm_f16<true, true><<<dim3(DIM / 256, (N_TOK + 127) / 128, 1), 256, SM_TOT>>>(
        xh, qwh, q_b, qh, N_TOK, DIM, DIM, 0, 0, 0);

    if (have_side) cudaStreamWaitEvent(0, evK, 0);     // need g_k
    attn_probs_kernel<<<dim3(NHEADS, N_T), 256>>>();

    if (have_side) cudaStreamWaitEvent(0, evSide, 0);  // need g_w2h
    gemm_f16<false, false><<<dim3(DIM / 256, (S_SP + 127) / 128, N_T), 256, SM_TOT>>>(
        probsh, w2h, p_b, out, S_SP, DIM, PKDIM,
        (size_t)S_SP * PKDIM, (size_t)DIM * PKDIM, (size_t)S_SP * DIM);
}

// round 10
// speedup vs baseline: 1.7063x; 1.7063x over previous
#include <cuda_runtime.h>
#include <cuda_fp16.h>
#include <cstdint>
#include <math.h>

// ---------------- fixed problem shapes ----------------
#define N_TOK   32760          // 21 * 1560
#define DIM     1536
#define NHEADS  12
#define HD      128
#define S_SP    1560
#define N_T     21
#define ENC     768
#define NA      32
#define KV_ROWS 672
#define PKDIM   384            // NHEADS * NA
#define LOG2_10000 13.287712379549449f

// ---------------- scratch ----------------
__device__ __half g_xh[N_TOK * DIM];          // fp16 x
__device__ __half g_qh[N_TOK * DIM];          // fp16 RoPE'd q
__device__ __half g_qwh[DIM * DIM];           // fp16 q_w
__device__ __half g_ehsh[KV_ROWS * ENC];      // fp16 encoder states
__device__ __half g_kvwh[2 * DIM * ENC];      // fp16 kv_w
__device__ float  g_kv[KV_ROWS * 2 * DIM];    // kv projection (fp32)
__device__ float  g_k[KV_ROWS * DIM];
__device__ float  g_v[KV_ROWS * DIM];
__device__ __half g_probsh[N_TOK * PKDIM];    // softmax probs [t*S+s][h*32+a]
__device__ __half g_w2h[N_T * DIM * PKDIM];   // W2^T [b][c][h*32+a]
__device__ float  g_pos[N_TOK];
__device__ float  g_mm[4];

// ---------------- helpers ----------------
__device__ __forceinline__ uint32_t smem_u32(const void* p) {
    uint32_t r;
    asm("{.reg .u64 t; cvta.to.shared.u64 t, %1; cvt.u32.u64 %0, t;}" : "=r"(r) : "l"(p));
    return r;
}

#define LDSM4(r0, r1, r2, r3, addr)                                            \
    asm volatile("ldmatrix.sync.aligned.m8n8.x4.shared.b16 {%0,%1,%2,%3}, [%4];" \
                 : "=r"(r0), "=r"(r1), "=r"(r2), "=r"(r3) : "r"(addr))

#define MMA_F16(d, a, b0, b1)                                                  \
    asm volatile("mma.sync.aligned.m16n8k16.row.col.f32.f16.f16.f32 "           \
                 "{%0,%1,%2,%3},{%4,%5,%6,%7},{%8,%9},{%0,%1,%2,%3};"          \
                 : "+f"(d[0]), "+f"(d[1]), "+f"(d[2]), "+f"(d[3])              \
                 : "r"(a[0]), "r"(a[1]), "r"(a[2]), "r"(a[3]), "r"(b0), "r"(b1))

// ---------------- fp32 -> fp16 conversion ----------------
__global__ void cvt_half_kernel(const float* __restrict__ in, __half* __restrict__ out, int n4) {
    int i = blockIdx.x * blockDim.x + threadIdx.x;
    if (i >= n4) return;
    float4 v = ((const float4*)in)[i];
    __half2 h0 = __floats2half2_rn(v.x, v.y);
    __half2 h1 = __floats2half2_rn(v.z, v.w);
    uint2 pk;
    pk.x = *(uint32_t*)&h0;
    pk.y = *(uint32_t*)&h1;
    ((uint2*)out)[i] = pk;
}

// ---------------- min/max of attn-map rows (single CTA, float4) ----------------
__global__ void minmax_kernel(const float* __restrict__ m) {
    __shared__ float s0[512], s1[512], s2[512], s3[512];
    int tid = threadIdx.x;
    float mn0 = 1e30f, mx0 = -1e30f, mn1 = 1e30f, mx1 = -1e30f;
    const float4* m0v = (const float4*)m;
    const float4* m1v = (const float4*)(m + N_TOK);
    for (int i = tid; i < N_TOK / 4; i += 512) {
        float4 v0 = m0v[i], v1 = m1v[i];
        mn0 = fminf(mn0, fminf(fminf(v0.x, v0.y), fminf(v0.z, v0.w)));
        mx0 = fmaxf(mx0, fmaxf(fmaxf(v0.x, v0.y), fmaxf(v0.z, v0.w)));
        mn1 = fminf(mn1, fminf(fminf(v1.x, v1.y), fminf(v1.z, v1.w)));
        mx1 = fmaxf(mx1, fmaxf(fmaxf(v1.x, v1.y), fmaxf(v1.z, v1.w)));
    }
    s0[tid] = mn0; s1[tid] = mx0; s2[tid] = mn1; s3[tid] = mx1;
    __syncthreads();
    for (int off = 256; off > 0; off >>= 1) {
        if (tid < off) {
            s0[tid] = fminf(s0[tid], s0[tid + off]);
            s1[tid] = fmaxf(s1[tid], s1[tid + off]);
            s2[tid] = fminf(s2[tid], s2[tid + off]);
            s3[tid] = fmaxf(s3[tid], s3[tid + off]);
        }
        __syncthreads();
    }
    if (tid == 0) { g_mm[0] = s0[0]; g_mm[1] = s1[0]; g_mm[2] = s2[0]; g_mm[3] = s3[0]; }
}

// ---------------- routing positions ----------------
__global__ void pos_kernel(const float* __restrict__ m) {
    int n = blockIdx.x * blockDim.x + threadIdx.x;
    if (n >= N_TOK) return;
    float m0 = m[n], m1 = m[N_TOK + n];
    float r;
    if (m0 >= m1) r = (m0 - g_mm[0]) / (g_mm[1] - g_mm[0] + 1e-8f) * 4.0f;
    else          r = (m1 - g_mm[2]) / (g_mm[3] - g_mm[2] + 1e-8f) * 4.0f + 20.0f;
    g_pos[n] = r;
}

// ======== big fp16 GEMM: CTA 128x256, 4-stage, occ 1 (long-K: the q projection) ========
#define KCHUNK  64
#define STAGES  4
#define SM_ASZ  16384
#define SM_BSZ  32768
#define SM_TOT  (STAGES * (SM_ASZ + SM_BSZ))   // 196608

__device__ __forceinline__ void fill_stage(
    const __half* __restrict__ A, const __half* __restrict__ B, int M, int K,
    int row0, int col0, int kt, uint32_t sA, uint32_t sB, int tid)
{
#pragma unroll
    for (int g = 0; g < 4; g++) {
        int ga = tid + g * 256;
        int row = ga >> 3, ch = ga & 7;
        uint32_t dst = sA + (uint32_t)row * 128u + (((uint32_t)ch * 16u) ^ (((uint32_t)row & 7u) << 4));
        const __half* src = A + (size_t)(row0 + row) * K + kt * KCHUNK + ch * 8;
        int sz = (row0 + row < M) ? 16 : 0;
        asm volatile("cp.async.cg.shared.global [%0], [%1], 16, %2;" :: "r"(dst), "l"(src), "r"(sz));
    }
#pragma unroll
    for (int g = 0; g < 8; g++) {
        int gb = tid + g * 256;
        int row = gb >> 3, ch = gb & 7;
        uint32_t dst = sB + (uint32_t)row * 128u + (((uint32_t)ch * 16u) ^ (((uint32_t)row & 7u) << 4));
        const __half* src = B + (size_t)(col0 + row) * K + kt * KCHUNK + ch * 8;
        asm volatile("cp.async.cg.shared.global [%0], [%1], 16;" :: "r"(dst), "l"(src));
    }
    asm volatile("cp.async.commit_group;");
}

template <bool FUSE_ROPE>
__global__ void __launch_bounds__(256, 1) gemm_f16_big(
    const __half* __restrict__ A, const __half* __restrict__ B,
    const float* __restrict__ bias, __half* __restrict__ C,
    int M, int N, int K)
{
    extern __shared__ float smem[];
    const int tid  = threadIdx.x;
    const int lane = tid & 31, warp = tid >> 5;
    const int wm = warp >> 2, wn = warp & 3;
    const int row0 = blockIdx.y * 128, col0 = blockIdx.x * 256;

    const uint32_t sA = smem_u32(smem);
    const uint32_t sB = sA + STAGES * SM_ASZ;
    const int ktiles = K / KCHUNK;

    fill_stage(A, B, M, K, row0, col0, 0, sA, sB, tid);
    fill_stage(A, B, M, K, row0, col0, 1, sA + SM_ASZ, sB + SM_BSZ, tid);
    fill_stage(A, B, M, K, row0, col0, 2, sA + 2 * SM_ASZ, sB + 2 * SM_BSZ, tid);

    float acc[4][8][4];
#pragma unroll
    for (int i = 0; i < 4; i++)
#pragma unroll
        for (int j = 0; j < 8; j++)
#pragma unroll
            for (int k = 0; k < 4; k++) acc[i][j][k] = 0.0f;

    const int aRow = wm * 64 + ((lane >> 3) & 1) * 8 + (lane & 7);
    const int bRow = wn * 64 + ((lane >> 3) & 1) * 8 + (lane & 7);
    const uint32_t colSel = ((lane >> 4) & 1) * 16;
    const uint32_t xorv = ((uint32_t)lane & 7u) << 4;

    for (int it = 0; it < ktiles; it++) {
        if (it < ktiles - 2)       asm volatile("cp.async.wait_group 2;" ::: "memory");
        else if (it == ktiles - 2) asm volatile("cp.async.wait_group 1;" ::: "memory");
        else                       asm volatile("cp.async.wait_group 0;" ::: "memory");
        __syncthreads();
        const int st = it & 3;
        const uint32_t bA = sA + st * SM_ASZ;
        const uint32_t bB = sB + st * SM_BSZ;
#pragma unroll
        for (int ks = 0; ks < 4; ks++) {
            uint32_t a[4][4], bb[4][4];
            const uint32_t cb = ((uint32_t)(ks * 32) + colSel) ^ xorv;
#pragma unroll
            for (int mf = 0; mf < 4; mf++) {
                uint32_t ad = bA + (uint32_t)(aRow + mf * 16) * 128 + cb;
                LDSM4(a[mf][0], a[mf][1], a[mf][2], a[mf][3], ad);
            }
#pragma unroll
            for (int ng = 0; ng < 4; ng++) {
                uint32_t bd = bB + (uint32_t)(bRow + ng * 16) * 128 + cb;
                LDSM4(bb[ng][0], bb[ng][1], bb[ng][2], bb[ng][3], bd);
            }
#pragma unroll
            for (int mf = 0; mf < 4; mf++)
#pragma unroll
                for (int nf = 0; nf < 8; nf++) {
                    const int ng = nf >> 1, lo = nf & 1;
                    MMA_F16(acc[mf][nf], a[mf], bb[ng][lo], bb[ng][2 + lo]);
                }
        }
        if (it + 3 < ktiles) {
            const int r = it + 3;
            fill_stage(A, B, M, K, row0, col0, r,
                       sA + (r & 3) * SM_ASZ, sB + (r & 3) * SM_BSZ, tid);
        }
    }

#pragma unroll
    for (int mf = 0; mf < 4; mf++) {
        const int r0 = row0 + wm * 64 + mf * 16 + (lane >> 2);
        const int r8 = r0 + 8;
        float pos0 = 0.f, pos8 = 0.f;
        if (FUSE_ROPE) {
            pos0 = g_pos[(r0 < M) ? r0 : 0];
            pos8 = g_pos[(r8 < M) ? r8 : 0];
        }
#pragma unroll
        for (int nf = 0; nf < 8; nf++) {
            const int c = col0 + wn * 64 + nf * 8 + (lane & 3) * 2;
            const float2 bv = *(const float2*)(bias + c);
            float o0 = acc[mf][nf][0] + bv.x;
            float o1 = acc[mf][nf][1] + bv.y;
            float o2 = acc[mf][nf][2] + bv.x;
            float o3 = acc[mf][nf][3] + bv.y;
            if (FUSE_ROPE) {
                const int i = (c & 127) >> 1;
                const float fr = exp2f(-(float)i * (LOG2_10000 / 64.0f));
                float sn, cs;
                sincosf(pos0 * fr, &sn, &cs);
                float t0 = o0 * cs - o1 * sn;
                o1 = o1 * cs + o0 * sn; o0 = t0;
                sincosf(pos8 * fr, &sn, &cs);
                float t2 = o2 * cs - o3 * sn;
                o3 = o3 * cs + o2 * sn; o2 = t2;
            }
            if (r0 < M) *(__half2*)(C + (size_t)r0 * N + c) = __floats2half2_rn(o0, o1);
            if (r8 < M) *(__half2*)(C + (size_t)r8 * N + c) = __floats2half2_rn(o2, o3);
        }
    }
}

// ======== small fp16 GEMM: CTA 128x128, 3-stage, occ 2 (short-K: kv + final) ========
#define SSTAGES 3
#define SSM_SZ  16384                           // 128 rows x 128 B (A and B each)
#define SSM_TOT (SSTAGES * 2 * SSM_SZ)          // 98304

__device__ __forceinline__ void fill_stage_s(
    const __half* __restrict__ A, const __half* __restrict__ B, int M, int K,
    int row0, int col0, int kt, uint32_t sA, uint32_t sB, int tid)
{
#pragma unroll
    for (int g = 0; g < 4; g++) {
        int ga = tid + g * 256;
        int row = ga >> 3, ch = ga & 7;
        uint32_t dst = sA + (uint32_t)row * 128u + (((uint32_t)ch * 16u) ^ (((uint32_t)row & 7u) << 4));
        const __half* src = A + (size_t)(row0 + row) * K + kt * KCHUNK + ch * 8;
        int sz = (row0 + row < M) ? 16 : 0;
        asm volatile("cp.async.cg.shared.global [%0], [%1], 16, %2;" :: "r"(dst), "l"(src), "r"(sz));
    }
#pragma unroll
    for (int g = 0; g < 4; g++) {
        int gb = tid + g * 256;
        int row = gb >> 3, ch = gb & 7;
        uint32_t dst = sB + (uint32_t)row * 128u + (((uint32_t)ch * 16u) ^ (((uint32_t)row & 7u) << 4));
        const __half* src = B + (size_t)(col0 + row) * K + kt * KCHUNK + ch * 8;
        asm volatile("cp.async.cg.shared.global [%0], [%1], 16;" :: "r"(dst), "l"(src));
    }
    asm volatile("cp.async.commit_group;");
}

__global__ void __launch_bounds__(256, 2) gemm_f16_small(
    const __half* __restrict__ A, const __half* __restrict__ B,
    const float* __restrict__ bias, float* __restrict__ Cv,
    int M, int N, int K, size_t strA, size_t strB, size_t strC)
{
    extern __shared__ float smem[];
    const int tid  = threadIdx.x;
    const int lane = tid & 31, warp = tid >> 5;
    const int wm = warp >> 2, wn = warp & 3;      // 2x4 warp grid, warp tile 64x32
    const int row0 = blockIdx.y * 128, col0 = blockIdx.x * 128;

    A += (size_t)blockIdx.z * strA;
    B += (size_t)blockIdx.z * strB;
    float* C = Cv + (size_t)blockIdx.z * strC;

    const uint32_t sA = smem_u32(smem);
    const uint32_t sB = sA + SSTAGES * SSM_SZ;
    const int ktiles = K / KCHUNK;

    fill_stage_s(A, B, M, K, row0, col0, 0, sA, sB, tid);
    fill_stage_s(A, B, M, K, row0, col0, 1, sA + SSM_SZ, sB + SSM_SZ, tid);

    float acc[4][4][4];
#pragma unroll
    for (int i = 0; i < 4; i++)
#pragma unroll
        for (int j = 0; j < 4; j++)
#pragma unroll
            for (int k = 0; k < 4; k++) acc[i][j][k] = 0.0f;

    const int aRow = wm * 64 + ((lane >> 3) & 1) * 8 + (lane & 7);
    const int bRow = wn * 32 + ((lane >> 3) & 1) * 8 + (lane & 7);
    const uint32_t colSel = ((lane >> 4) & 1) * 16;
    const uint32_t xorv = ((uint32_t)lane & 7u) << 4;

    for (int it = 0; it < ktiles; it++) {
        if (it < ktiles - 1) asm volatile("cp.async.wait_group 1;" ::: "memory");
        else                 asm volatile("cp.async.wait_group 0;" ::: "memory");
        __syncthreads();
        const int st = it % 3;
        const uint32_t bA = sA + st * SSM_SZ;
        const uint32_t bB = sB + st * SSM_SZ;
#pragma unroll
        for (int ks = 0; ks < 4; ks++) {
            uint32_t a[4][4], bb[2][4];
            const uint32_t cb = ((uint32_t)(ks * 32) + colSel) ^ xorv;
#pragma unroll
            for (int mf = 0; mf < 4; mf++) {
                uint32_t ad = bA + (uint32_t)(aRow + mf * 16) * 128 + cb;
                LDSM4(a[mf][0], a[mf][1], a[mf][2], a[mf][3], ad);
            }
#pragma unroll
            for (int ng = 0; ng < 2; ng++) {
                uint32_t bd = bB + (uint32_t)(bRow + ng * 16) * 128 + cb;
                LDSM4(bb[ng][0], bb[ng][1], bb[ng][2], bb[ng][3], bd);
            }
#pragma unroll
            for (int mf = 0; mf < 4; mf++)
#pragma unroll
                for (int nf = 0; nf < 4; nf++) {
                    const int ng = nf >> 1, lo = nf & 1;
                    MMA_F16(acc[mf][nf], a[mf], bb[ng][lo], bb[ng][2 + lo]);
                }
        }
        if (it + 2 < ktiles) {
            const int r = it + 2;
            fill_stage_s(A, B, M, K, row0, col0, r,
                         sA + (r % 3) * SSM_SZ, sB + (r % 3) * SSM_SZ, tid);
        }
    }

#pragma unroll
    for (int mf = 0; mf < 4; mf++) {
        const int r0 = row0 + wm * 64 + mf * 16 + (lane >> 2);
        const int r8 = r0 + 8;
#pragma unroll
        for (int nf = 0; nf < 4; nf++) {
            const int c = col0 + wn * 32 + nf * 8 + (lane & 3) * 2;
            const float2 bv = *(const float2*)(bias + c);
            if (r0 < M) *(float2*)(C + (size_t)r0 * N + c) =
                make_float2(acc[mf][nf][0] + bv.x, acc[mf][nf][1] + bv.y);
            if (r8 < M) *(float2*)(C + (size_t)r8 * N + c) =
                make_float2(acc[mf][nf][2] + bv.x, acc[mf][nf][3] + bv.y);
        }
    }
}

// ---------------- split kv -> k (bucket-centre RoPE) and v ----------------
__global__ void rope_k_split_kernel() {
    int idx = blockIdx.x * blockDim.x + threadIdx.x;
    if (idx >= KV_ROWS * (DIM / 2)) return;
    int r = idx / (DIM / 2);
    int p = idx - r * (DIM / 2);
    int a = r & 31;
    float pos = (a < 16) ? 2.0f : 22.0f;
    int i = p & 63;
    float fr = exp2f(-(float)i * (LOG2_10000 / 64.0f));
    float th = pos * fr;
    float s, c;
    sincosf(th, &s, &c);
    const float* kvr = g_kv + (size_t)r * (2 * DIM);
    float ka = kvr[2 * p], kb = kvr[2 * p + 1];
    size_t o = (size_t)r * DIM + 2 * p;
    g_k[o]     = ka * c - kb * s;
    g_k[o + 1] = kb * c + ka * s;
    g_v[o]     = kvr[DIM + 2 * p];
    g_v[o + 1] = kvr[DIM + 2 * p + 1];
}

// ---------------- attention probs (s-split 4-way for load balance) ----------
#define S_CHUNK 390
__global__ void __launch_bounds__(256) attn_probs_kernel() {
    const int h = blockIdx.x;
    const int t = blockIdx.y;
    const int chunk = blockIdx.z;
    __shared__ float ks[32][129];
    __shared__ __half qs[8][128];

    const int tid = threadIdx.x;
    for (int i = tid; i < 32 * 128; i += 256) {
        int a = i >> 7, d = i & 127;
        ks[a][d] = g_k[(size_t)(t * 32 + a) * DIM + h * HD + d];
    }
    __syncthreads();

    const int w = tid >> 5, l = tid & 31;
    const int sBeg = chunk * S_CHUNK;
    const int sEnd = (sBeg + S_CHUNK < S_SP) ? sBeg + S_CHUNK : S_SP;

    for (int s = sBeg + w; s < sEnd; s += 8) {
        size_t qoff = (size_t)(t * S_SP + s) * DIM + h * HD;
        ((uint2*)&qs[w][0])[l] = *(const uint2*)(g_qh + qoff + 4 * l);
        __syncwarp();

        float acc = 0.0f;
        const __half2* q2 = (const __half2*)&qs[w][0];
        const float* kr = &ks[l][0];
#pragma unroll
        for (int j = 0; j < 64; j++) {
            float2 qf = __half22float2(q2[j]);
            acc += qf.x * kr[2 * j] + qf.y * kr[2 * j + 1];
        }
        acc *= 0.08838834764831845f;

        float mx = acc;
#pragma unroll
        for (int o = 16; o > 0; o >>= 1) mx = fmaxf(mx, __shfl_xor_sync(0xFFFFFFFFu, mx, o));
        float e = __expf(acc - mx);
        float sum = e;
#pragma unroll
        for (int o = 16; o > 0; o >>= 1) sum += __shfl_xor_sync(0xFFFFFFFFu, sum, o);
        float p = e / sum;

        g_probsh[(size_t)(t * S_SP + s) * PKDIM + h * NA + l] = __float2half_rn(p);
        __syncwarp();
    }
}

// ---------------- W2[b,h] = V[b,h] @ proj_slice_h  (rank-32 fold of proj) -----
__global__ void __launch_bounds__(128) w2_kernel(const float* __restrict__ pw) {
    const int ct = blockIdx.x;
    const int h  = blockIdx.y;
    const int b  = blockIdx.z;
    __shared__ float Vs[32][128];

    const int tid = threadIdx.x;
    for (int i = tid; i < 32 * 128; i += 128) {
        int a = i >> 7, d = i & 127;
        Vs[a][d] = g_v[(size_t)(b * 32 + a) * DIM + h * HD + d];
    }
    __syncthreads();

    const int c = ct * 128 + tid;
    float acc[32];
#pragma unroll
    for (int a = 0; a < 32; a++) acc[a] = 0.0f;

    const float* pwr = pw + (size_t)c * DIM + h * HD;
#pragma unroll
    for (int chunk = 0; chunk < 4; chunk++) {
        float pr[32];
#pragma unroll
        for (int j = 0; j < 8; j++) {
            float4 v4 = *(const float4*)(pwr + chunk * 32 + j * 4);
            pr[j * 4 + 0] = v4.x; pr[j * 4 + 1] = v4.y;
            pr[j * 4 + 2] = v4.z; pr[j * 4 + 3] = v4.w;
        }
#pragma unroll
        for (int a = 0; a < 32; a++) {
#pragma unroll
            for (int j = 0; j < 32; j++)
                acc[a] += pr[j] * Vs[a][chunk * 32 + j];
        }
    }

    __half* dst = g_w2h + (size_t)b * DIM * PKDIM + (size_t)c * PKDIM + h * NA;
#pragma unroll
    for (int a = 0; a < 32; a += 2)
        *(__half2*)(dst + a) = __floats2half2_rn(acc[a], acc[a + 1]);
}

// ---------------- launch (single stream — fork-join measured slower) ---------
extern "C" void kernel_launch(void* const* d_in, const int* in_sizes, int n_in,
                              void* d_out, int out_size)
{
    const float* x    = (const float*)d_in[0];
    const float* ehs  = (const float*)d_in[1];
    const float* amap = (const float*)d_in[2];
    const float* q_w  = (const float*)d_in[3];
    const float* q_b  = (const float*)d_in[4];
    const float* kv_w = (const float*)d_in[5];
    const float* kv_b = (const float*)d_in[6];
    const float* p_w  = (const float*)d_in[7];
    const float* p_b  = (const float*)d_in[8];
    float* out = (float*)d_out;

    __half *xh, *qh, *qwh, *ehsh, *kvwh, *probsh, *w2h;
    float *kv;
    cudaGetSymbolAddress((void**)&xh,     g_xh);
    cudaGetSymbolAddress((void**)&qh,     g_qh);
    cudaGetSymbolAddress((void**)&qwh,    g_qwh);
    cudaGetSymbolAddress((void**)&ehsh,   g_ehsh);
    cudaGetSymbolAddress((void**)&kvwh,   g_kvwh);
    cudaGetSymbolAddress((void**)&probsh, g_probsh);
    cudaGetSymbolAddress((void**)&w2h,    g_w2h);
    cudaGetSymbolAddress((void**)&kv,     g_kv);

    cudaFuncSetAttribute((const void*)gemm_f16_big<true>,
                         cudaFuncAttributeMaxDynamicSharedMemorySize, SM_TOT);
    cudaFuncSetAttribute((const void*)gemm_f16_small,
                         cudaFuncAttributeMaxDynamicSharedMemorySize, SSM_TOT);

    // routing positions
    minmax_kernel<<<1, 512>>>(amap);
    pos_kernel<<<(N_TOK + 255) / 256, 256>>>(amap);

    // fp16 conversions
    cvt_half_kernel<<<(N_TOK * DIM / 4 + 255) / 256, 256>>>(x, xh, N_TOK * DIM / 4);
    cvt_half_kernel<<<(DIM * DIM / 4 + 255) / 256, 256>>>(q_w, qwh, DIM * DIM / 4);
    cvt_half_kernel<<<(KV_ROWS * ENC / 4 + 255) / 256, 256>>>(ehs, ehsh, KV_ROWS * ENC / 4);
    cvt_half_kernel<<<(2 * DIM * ENC / 4 + 255) / 256, 256>>>(kv_w, kvwh, 2 * DIM * ENC / 4);

    // q = RoPE(x @ q_w^T + q_b) -> fp16   (big GEMM, occ-1 deep pipeline)
    gemm_f16_big<true><<<dim3(DIM / 256, (N_TOK + 127) / 128), 256, SM_TOT>>>(
        xh, qwh, q_b, qh, N_TOK, DIM, DIM);

    // kv = ehs @ kv_w^T + kv_b -> fp32   (small GEMM, occ 2)
    gemm_f16_small<<<dim3((2 * DIM) / 128, (KV_ROWS + 127) / 128, 1), 256, SSM_TOT>>>(
        ehsh, kvwh, kv_b, kv, KV_ROWS, 2 * DIM, ENC, 0, 0, 0);

    // split + RoPE(k)
    rope_k_split_kernel<<<(KV_ROWS * (DIM / 2) + 255) / 256, 256>>>();

    // attention probabilities (s-split for balance)
    attn_probs_kernel<<<dim3(NHEADS, N_T, 4), 256>>>();

    // W2 = V @ proj (per frame, per head) -> fp16 [b][c][h*32+a]
    w2_kernel<<<dim3(DIM / 128, NHEADS, N_T), 128>>>(p_w);

    // out[b] = probs[b] @ W2[b]^T + p_b   (batched, K=384, small GEMM occ 2)
    gemm_f16_small<<<dim3(DIM / 128, (S_SP + 127) / 128, N_T), 256, SSM_TOT>>>(
        probsh, w2h, p_b, out, S_SP, DIM, PKDIM,
        (size_t)S_SP * PKDIM, (size_t)DIM * PKDIM, (size_t)S_SP * DIM);
}

// round 11
// speedup vs baseline: 1.8429x; 1.0801x over previous
#include <cuda_runtime.h>
#include <cuda_fp16.h>
#include <cstdint>
#include <math.h>

// ---------------- fixed problem shapes ----------------
#define N_TOK   32760          // 21 * 1560
#define DIM     1536
#define NHEADS  12
#define HD      128
#define S_SP    1560
#define N_T     21
#define ENC     768
#define NA      32
#define KV_ROWS 672
#define PKDIM   384            // NHEADS * NA
#define LOG2_10000 13.287712379549449f

// ---------------- scratch ----------------
__device__ __half g_xh[N_TOK * DIM];          // fp16 x
__device__ __half g_qh[N_TOK * DIM];          // fp16 RoPE'd q
__device__ __half g_qwh[DIM * DIM];           // fp16 q_w
__device__ __half g_pwh[DIM * DIM];           // fp16 proj_w
__device__ __half g_ehsh[KV_ROWS * ENC];      // fp16 encoder states
__device__ __half g_kvwh[2 * DIM * ENC];      // fp16 kv_w
__device__ float  g_kv[KV_ROWS * 2 * DIM];    // kv projection (fp32)
__device__ float  g_k[KV_ROWS * DIM];         // RoPE'd k (fp32)
__device__ __half g_vh[KV_ROWS * DIM];        // v (fp16, consumed by W2 fold)
__device__ __half g_probsh[N_TOK * PKDIM];    // softmax probs [t*S+s][h*32+a]
__device__ __half g_w2h[N_T * DIM * PKDIM];   // W2^T [b][c][h*32+a]
__device__ float  g_pos[N_TOK];
__device__ float  g_mm[4];

// ---------------- helpers ----------------
__device__ __forceinline__ uint32_t smem_u32(const void* p) {
    uint32_t r;
    asm("{.reg .u64 t; cvta.to.shared.u64 t, %1; cvt.u32.u64 %0, t;}" : "=r"(r) : "l"(p));
    return r;
}

#define LDSM4(r0, r1, r2, r3, addr)                                            \
    asm volatile("ldmatrix.sync.aligned.m8n8.x4.shared.b16 {%0,%1,%2,%3}, [%4];" \
                 : "=r"(r0), "=r"(r1), "=r"(r2), "=r"(r3) : "r"(addr))

#define MMA_F16(d, a, b0, b1)                                                  \
    asm volatile("mma.sync.aligned.m16n8k16.row.col.f32.f16.f16.f32 "           \
                 "{%0,%1,%2,%3},{%4,%5,%6,%7},{%8,%9},{%0,%1,%2,%3};"          \
                 : "+f"(d[0]), "+f"(d[1]), "+f"(d[2]), "+f"(d[3])              \
                 : "r"(a[0]), "r"(a[1]), "r"(a[2]), "r"(a[3]), "r"(b0), "r"(b1))

// ---------------- fp32 -> fp16 conversion ----------------
__global__ void cvt_half_kernel(const float* __restrict__ in, __half* __restrict__ out, int n4) {
    int i = blockIdx.x * blockDim.x + threadIdx.x;
    if (i >= n4) return;
    float4 v = ((const float4*)in)[i];
    __half2 h0 = __floats2half2_rn(v.x, v.y);
    __half2 h1 = __floats2half2_rn(v.z, v.w);
    uint2 pk;
    pk.x = *(uint32_t*)&h0;
    pk.y = *(uint32_t*)&h1;
    ((uint2*)out)[i] = pk;
}

// ---------------- min/max of attn-map rows (single CTA, float4) ----------------
__global__ void minmax_kernel(const float* __restrict__ m) {
    __shared__ float s0[512], s1[512], s2[512], s3[512];
    int tid = threadIdx.x;
    float mn0 = 1e30f, mx0 = -1e30f, mn1 = 1e30f, mx1 = -1e30f;
    const float4* m0v = (const float4*)m;
    const float4* m1v = (const float4*)(m + N_TOK);
    for (int i = tid; i < N_TOK / 4; i += 512) {
        float4 v0 = m0v[i], v1 = m1v[i];
        mn0 = fminf(mn0, fminf(fminf(v0.x, v0.y), fminf(v0.z, v0.w)));
        mx0 = fmaxf(mx0, fmaxf(fmaxf(v0.x, v0.y), fmaxf(v0.z, v0.w)));
        mn1 = fminf(mn1, fminf(fminf(v1.x, v1.y), fminf(v1.z, v1.w)));
        mx1 = fmaxf(mx1, fmaxf(fmaxf(v1.x, v1.y), fmaxf(v1.z, v1.w)));
    }
    s0[tid] = mn0; s1[tid] = mx0; s2[tid] = mn1; s3[tid] = mx1;
    __syncthreads();
    for (int off = 256; off > 0; off >>= 1) {
        if (tid < off) {
            s0[tid] = fminf(s0[tid], s0[tid + off]);
            s1[tid] = fmaxf(s1[tid], s1[tid + off]);
            s2[tid] = fminf(s2[tid], s2[tid + off]);
            s3[tid] = fmaxf(s3[tid], s3[tid + off]);
        }
        __syncthreads();
    }
    if (tid == 0) { g_mm[0] = s0[0]; g_mm[1] = s1[0]; g_mm[2] = s2[0]; g_mm[3] = s3[0]; }
}

// ---------------- routing positions ----------------
__global__ void pos_kernel(const float* __restrict__ m) {
    int n = blockIdx.x * blockDim.x + threadIdx.x;
    if (n >= N_TOK) return;
    float m0 = m[n], m1 = m[N_TOK + n];
    float r;
    if (m0 >= m1) r = (m0 - g_mm[0]) / (g_mm[1] - g_mm[0] + 1e-8f) * 4.0f;
    else          r = (m1 - g_mm[2]) / (g_mm[3] - g_mm[2] + 1e-8f) * 4.0f + 20.0f;
    g_pos[n] = r;
}

// ======== big fp16 GEMM: CTA 128x256, 4-stage, occ 1 (long-K: the q projection) ========
#define KCHUNK  64
#define STAGES  4
#define SM_ASZ  16384
#define SM_BSZ  32768
#define SM_TOT  (STAGES * (SM_ASZ + SM_BSZ))   // 196608

__device__ __forceinline__ void fill_stage(
    const __half* __restrict__ A, const __half* __restrict__ B, int M, int K,
    int row0, int col0, int kt, uint32_t sA, uint32_t sB, int tid)
{
#pragma unroll
    for (int g = 0; g < 4; g++) {
        int ga = tid + g * 256;
        int row = ga >> 3, ch = ga & 7;
        uint32_t dst = sA + (uint32_t)row * 128u + (((uint32_t)ch * 16u) ^ (((uint32_t)row & 7u) << 4));
        const __half* src = A + (size_t)(row0 + row) * K + kt * KCHUNK + ch * 8;
        int sz = (row0 + row < M) ? 16 : 0;
        asm volatile("cp.async.cg.shared.global [%0], [%1], 16, %2;" :: "r"(dst), "l"(src), "r"(sz));
    }
#pragma unroll
    for (int g = 0; g < 8; g++) {
        int gb = tid + g * 256;
        int row = gb >> 3, ch = gb & 7;
        uint32_t dst = sB + (uint32_t)row * 128u + (((uint32_t)ch * 16u) ^ (((uint32_t)row & 7u) << 4));
        const __half* src = B + (size_t)(col0 + row) * K + kt * KCHUNK + ch * 8;
        asm volatile("cp.async.cg.shared.global [%0], [%1], 16;" :: "r"(dst), "l"(src));
    }
    asm volatile("cp.async.commit_group;");
}

template <bool FUSE_ROPE>
__global__ void __launch_bounds__(256, 1) gemm_f16_big(
    const __half* __restrict__ A, const __half* __restrict__ B,
    const float* __restrict__ bias, __half* __restrict__ C,
    int M, int N, int K)
{
    extern __shared__ float smem[];
    const int tid  = threadIdx.x;
    const int lane = tid & 31, warp = tid >> 5;
    const int wm = warp >> 2, wn = warp & 3;
    const int row0 = blockIdx.y * 128, col0 = blockIdx.x * 256;

    const uint32_t sA = smem_u32(smem);
    const uint32_t sB = sA + STAGES * SM_ASZ;
    const int ktiles = K / KCHUNK;

    fill_stage(A, B, M, K, row0, col0, 0, sA, sB, tid);
    fill_stage(A, B, M, K, row0, col0, 1, sA + SM_ASZ, sB + SM_BSZ, tid);
    fill_stage(A, B, M, K, row0, col0, 2, sA + 2 * SM_ASZ, sB + 2 * SM_BSZ, tid);

    float acc[4][8][4];
#pragma unroll
    for (int i = 0; i < 4; i++)
#pragma unroll
        for (int j = 0; j < 8; j++)
#pragma unroll
            for (int k = 0; k < 4; k++) acc[i][j][k] = 0.0f;

    const int aRow = wm * 64 + ((lane >> 3) & 1) * 8 + (lane & 7);
    const int bRow = wn * 64 + ((lane >> 3) & 1) * 8 + (lane & 7);
    const uint32_t colSel = ((lane >> 4) & 1) * 16;
    const uint32_t xorv = ((uint32_t)lane & 7u) << 4;

    for (int it = 0; it < ktiles; it++) {
        if (it < ktiles - 2)       asm volatile("cp.async.wait_group 2;" ::: "memory");
        else if (it == ktiles - 2) asm volatile("cp.async.wait_group 1;" ::: "memory");
        else                       asm volatile("cp.async.wait_group 0;" ::: "memory");
        __syncthreads();
        const int st = it & 3;
        const uint32_t bA = sA + st * SM_ASZ;
        const uint32_t bB = sB + st * SM_BSZ;
#pragma unroll
        for (int ks = 0; ks < 4; ks++) {
            uint32_t a[4][4], bb[4][4];
            const uint32_t cb = ((uint32_t)(ks * 32) + colSel) ^ xorv;
#pragma unroll
            for (int mf = 0; mf < 4; mf++) {
                uint32_t ad = bA + (uint32_t)(aRow + mf * 16) * 128 + cb;
                LDSM4(a[mf][0], a[mf][1], a[mf][2], a[mf][3], ad);
            }
#pragma unroll
            for (int ng = 0; ng < 4; ng++) {
                uint32_t bd = bB + (uint32_t)(bRow + ng * 16) * 128 + cb;
                LDSM4(bb[ng][0], bb[ng][1], bb[ng][2], bb[ng][3], bd);
            }
#pragma unroll
            for (int mf = 0; mf < 4; mf++)
#pragma unroll
                for (int nf = 0; nf < 8; nf++) {
                    const int ng = nf >> 1, lo = nf & 1;
                    MMA_F16(acc[mf][nf], a[mf], bb[ng][lo], bb[ng][2 + lo]);
                }
        }
        if (it + 3 < ktiles) {
            const int r = it + 3;
            fill_stage(A, B, M, K, row0, col0, r,
                       sA + (r & 3) * SM_ASZ, sB + (r & 3) * SM_BSZ, tid);
        }
    }

#pragma unroll
    for (int mf = 0; mf < 4; mf++) {
        const int r0 = row0 + wm * 64 + mf * 16 + (lane >> 2);
        const int r8 = r0 + 8;
        float pos0 = 0.f, pos8 = 0.f;
        if (FUSE_ROPE) {
            pos0 = g_pos[(r0 < M) ? r0 : 0];
            pos8 = g_pos[(r8 < M) ? r8 : 0];
        }
#pragma unroll
        for (int nf = 0; nf < 8; nf++) {
            const int c = col0 + wn * 64 + nf * 8 + (lane & 3) * 2;
            const float2 bv = *(const float2*)(bias + c);
            float o0 = acc[mf][nf][0] + bv.x;
            float o1 = acc[mf][nf][1] + bv.y;
            float o2 = acc[mf][nf][2] + bv.x;
            float o3 = acc[mf][nf][3] + bv.y;
            if (FUSE_ROPE) {
                const int i = (c & 127) >> 1;
                const float fr = exp2f(-(float)i * (LOG2_10000 / 64.0f));
                float sn, cs;
                sincosf(pos0 * fr, &sn, &cs);
                float t0 = o0 * cs - o1 * sn;
                o1 = o1 * cs + o0 * sn; o0 = t0;
                sincosf(pos8 * fr, &sn, &cs);
                float t2 = o2 * cs - o3 * sn;
                o3 = o3 * cs + o2 * sn; o2 = t2;
            }
            if (r0 < M) *(__half2*)(C + (size_t)r0 * N + c) = __floats2half2_rn(o0, o1);
            if (r8 < M) *(__half2*)(C + (size_t)r8 * N + c) = __floats2half2_rn(o2, o3);
        }
    }
}

// ======== small fp16 GEMM: CTA 128x128, 3-stage, occ 2 (short-K: kv + final) ========
#define SSTAGES 3
#define SSM_SZ  16384
#define SSM_TOT (SSTAGES * 2 * SSM_SZ)          // 98304

__device__ __forceinline__ void fill_stage_s(
    const __half* __restrict__ A, const __half* __restrict__ B, int M, int K,
    int row0, int col0, int kt, uint32_t sA, uint32_t sB, int tid)
{
#pragma unroll
    for (int g = 0; g < 4; g++) {
        int ga = tid + g * 256;
        int row = ga >> 3, ch = ga & 7;
        uint32_t dst = sA + (uint32_t)row * 128u + (((uint32_t)ch * 16u) ^ (((uint32_t)row & 7u) << 4));
        const __half* src = A + (size_t)(row0 + row) * K + kt * KCHUNK + ch * 8;
        int sz = (row0 + row < M) ? 16 : 0;
        asm volatile("cp.async.cg.shared.global [%0], [%1], 16, %2;" :: "r"(dst), "l"(src), "r"(sz));
    }
#pragma unroll
    for (int g = 0; g < 4; g++) {
        int gb = tid + g * 256;
        int row = gb >> 3, ch = gb & 7;
        uint32_t dst = sB + (uint32_t)row * 128u + (((uint32_t)ch * 16u) ^ (((uint32_t)row & 7u) << 4));
        const __half* src = B + (size_t)(col0 + row) * K + kt * KCHUNK + ch * 8;
        asm volatile("cp.async.cg.shared.global [%0], [%1], 16;" :: "r"(dst), "l"(src));
    }
    asm volatile("cp.async.commit_group;");
}

__global__ void __launch_bounds__(256, 2) gemm_f16_small(
    const __half* __restrict__ A, const __half* __restrict__ B,
    const float* __restrict__ bias, float* __restrict__ Cv,
    int M, int N, int K, size_t strA, size_t strB, size_t strC)
{
    extern __shared__ float smem[];
    const int tid  = threadIdx.x;
    const int lane = tid & 31, warp = tid >> 5;
    const int wm = warp >> 2, wn = warp & 3;
    const int row0 = blockIdx.y * 128, col0 = blockIdx.x * 128;

    A += (size_t)blockIdx.z * strA;
    B += (size_t)blockIdx.z * strB;
    float* C = Cv + (size_t)blockIdx.z * strC;

    const uint32_t sA = smem_u32(smem);
    const uint32_t sB = sA + SSTAGES * SSM_SZ;
    const int ktiles = K / KCHUNK;

    fill_stage_s(A, B, M, K, row0, col0, 0, sA, sB, tid);
    fill_stage_s(A, B, M, K, row0, col0, 1, sA + SSM_SZ, sB + SSM_SZ, tid);

    float acc[4][4][4];
#pragma unroll
    for (int i = 0; i < 4; i++)
#pragma unroll
        for (int j = 0; j < 4; j++)
#pragma unroll
            for (int k = 0; k < 4; k++) acc[i][j][k] = 0.0f;

    const int aRow = wm * 64 + ((lane >> 3) & 1) * 8 + (lane & 7);
    const int bRow = wn * 32 + ((lane >> 3) & 1) * 8 + (lane & 7);
    const uint32_t colSel = ((lane >> 4) & 1) * 16;
    const uint32_t xorv = ((uint32_t)lane & 7u) << 4;

    for (int it = 0; it < ktiles; it++) {
        if (it < ktiles - 1) asm volatile("cp.async.wait_group 1;" ::: "memory");
        else                 asm volatile("cp.async.wait_group 0;" ::: "memory");
        __syncthreads();
        const int st = it % 3;
        const uint32_t bA = sA + st * SSM_SZ;
        const uint32_t bB = sB + st * SSM_SZ;
#pragma unroll
        for (int ks = 0; ks < 4; ks++) {
            uint32_t a[4][4], bb[2][4];
            const uint32_t cb = ((uint32_t)(ks * 32) + colSel) ^ xorv;
#pragma unroll
            for (int mf = 0; mf < 4; mf++) {
                uint32_t ad = bA + (uint32_t)(aRow + mf * 16) * 128 + cb;
                LDSM4(a[mf][0], a[mf][1], a[mf][2], a[mf][3], ad);
            }
#pragma unroll
            for (int ng = 0; ng < 2; ng++) {
                uint32_t bd = bB + (uint32_t)(bRow + ng * 16) * 128 + cb;
                LDSM4(bb[ng][0], bb[ng][1], bb[ng][2], bb[ng][3], bd);
            }
#pragma unroll
            for (int mf = 0; mf < 4; mf++)
#pragma unroll
                for (int nf = 0; nf < 4; nf++) {
                    const int ng = nf >> 1, lo = nf & 1;
                    MMA_F16(acc[mf][nf], a[mf], bb[ng][lo], bb[ng][2 + lo]);
                }
        }
        if (it + 2 < ktiles) {
            const int r = it + 2;
            fill_stage_s(A, B, M, K, row0, col0, r,
                         sA + (r % 3) * SSM_SZ, sB + (r % 3) * SSM_SZ, tid);
        }
    }

#pragma unroll
    for (int mf = 0; mf < 4; mf++) {
        const int r0 = row0 + wm * 64 + mf * 16 + (lane >> 2);
        const int r8 = r0 + 8;
#pragma unroll
        for (int nf = 0; nf < 4; nf++) {
            const int c = col0 + wn * 32 + nf * 8 + (lane & 3) * 2;
            const float2 bv = *(const float2*)(bias + c);
            if (r0 < M) *(float2*)(C + (size_t)r0 * N + c) =
                make_float2(acc[mf][nf][0] + bv.x, acc[mf][nf][1] + bv.y);
            if (r8 < M) *(float2*)(C + (size_t)r8 * N + c) =
                make_float2(acc[mf][nf][2] + bv.x, acc[mf][nf][3] + bv.y);
        }
    }
}

// ---------------- split kv -> k (RoPE, fp32) and v (fp16) ----------------
__global__ void rope_k_split_kernel() {
    int idx = blockIdx.x * blockDim.x + threadIdx.x;
    if (idx >= KV_ROWS * (DIM / 2)) return;
    int r = idx / (DIM / 2);
    int p = idx - r * (DIM / 2);
    int a = r & 31;
    float pos = (a < 16) ? 2.0f : 22.0f;
    int i = p & 63;
    float fr = exp2f(-(float)i * (LOG2_10000 / 64.0f));
    float th = pos * fr;
    float s, c;
    sincosf(th, &s, &c);
    const float* kvr = g_kv + (size_t)r * (2 * DIM);
    float ka = kvr[2 * p], kb = kvr[2 * p + 1];
    size_t o = (size_t)r * DIM + 2 * p;
    g_k[o]     = ka * c - kb * s;
    g_k[o + 1] = kb * c + ka * s;
    *(__half2*)(g_vh + o) = __floats2half2_rn(kvr[DIM + 2 * p], kvr[DIM + 2 * p + 1]);
}

// ---------------- attention probs (float-staged q; s-split 4-way) ----------
#define S_CHUNK 390
__global__ void __launch_bounds__(256) attn_probs_kernel() {
    const int h = blockIdx.x;
    const int t = blockIdx.y;
    const int chunk = blockIdx.z;
    __shared__ float ks[32][132];   // stride 132: float4 rows hit 8 distinct quads/subphase
    __shared__ float qs[8][128];

    const int tid = threadIdx.x;
    for (int i = tid; i < 32 * 128; i += 256) {
        int a = i >> 7, d = i & 127;
        ks[a][d] = g_k[(size_t)(t * 32 + a) * DIM + h * HD + d];
    }
    __syncthreads();

    const int w = tid >> 5, l = tid & 31;
    const int sBeg = chunk * S_CHUNK;
    const int sEnd = (sBeg + S_CHUNK < S_SP) ? sBeg + S_CHUNK : S_SP;

    for (int s = sBeg + w; s < sEnd; s += 8) {
        size_t qoff = (size_t)(t * S_SP + s) * DIM + h * HD;
        // stage q as float: convert once per row (4 cvt per lane), not in the dot loop
        uint2 qp = *(const uint2*)(g_qh + qoff + 4 * l);
        float2 f0 = __half22float2(*(__half2*)&qp.x);
        float2 f1 = __half22float2(*(__half2*)&qp.y);
        *(float4*)&qs[w][4 * l] = make_float4(f0.x, f0.y, f1.x, f1.y);
        __syncwarp();

        float acc = 0.0f;
        const float4* qr = (const float4*)&qs[w][0];
        const float4* kr = (const float4*)&ks[l][0];
#pragma unroll
        for (int j = 0; j < 32; j++) {
            float4 a4 = qr[j];
            float4 b4 = kr[j];
            acc += a4.x * b4.x + a4.y * b4.y + a4.z * b4.z + a4.w * b4.w;
        }
        acc *= 0.08838834764831845f;

        float mx = acc;
#pragma unroll
        for (int o = 16; o > 0; o >>= 1) mx = fmaxf(mx, __shfl_xor_sync(0xFFFFFFFFu, mx, o));
        float e = __expf(acc - mx);
        float sum = e;
#pragma unroll
        for (int o = 16; o > 0; o >>= 1) sum += __shfl_xor_sync(0xFFFFFFFFu, sum, o);
        float p = e / sum;

        g_probsh[(size_t)(t * S_SP + s) * PKDIM + h * NA + l] = __float2half_rn(p);
        __syncwarp();
    }
}

// ---------------- W2 fold on tensor cores ------------------------------------
// Per CTA (mt, h, b): W2_block[128 x 32] = pw_h[mt*128..+128, 128] @ V_{b,h}^T
// A = g_pwh rows (c), cols h*128+d (k-major). B = g_vh rows (a), dims d (k-major).
__global__ void __launch_bounds__(128) w2_mma_kernel() {
    const int mt = blockIdx.x;     // 0..11 (c tile)
    const int h  = blockIdx.y;     // 0..11
    const int b  = blockIdx.z;     // 0..20
    __shared__ __align__(16) char smem[2 * 16384 + 2 * 4096];  // A 2 kchunks + B 2 kchunks

    const int tid = threadIdx.x;
    const int lane = tid & 31, warp = tid >> 5;
    const uint32_t sA = smem_u32(smem);
    const uint32_t sB = sA + 2 * 16384;

    // load A: 2 kchunks x 128 rows x 8 x 16B  (2048 cp.async, 16/thread)
#pragma unroll
    for (int g = 0; g < 16; g++) {
        int i = tid + g * 128;
        int kt = i >> 10, row = (i >> 3) & 127, ch = i & 7;
        uint32_t dst = sA + kt * 16384 + (uint32_t)row * 128u +
                       (((uint32_t)ch * 16u) ^ (((uint32_t)row & 7u) << 4));
        const __half* src = g_pwh + (size_t)(mt * 128 + row) * DIM + h * HD + kt * KCHUNK + ch * 8;
        asm volatile("cp.async.cg.shared.global [%0], [%1], 16;" :: "r"(dst), "l"(src));
    }
    // load B: 2 kchunks x 32 rows x 8 x 16B  (512 cp.async, 4/thread)
#pragma unroll
    for (int g = 0; g < 4; g++) {
        int i = tid + g * 128;
        int kt = i >> 8, row = (i >> 3) & 31, ch = i & 7;
        uint32_t dst = sB + kt * 4096 + (uint32_t)row * 128u +
                       (((uint32_t)ch * 16u) ^ (((uint32_t)row & 7u) << 4));
        const __half* src = g_vh + (size_t)(b * 32 + row) * DIM + h * HD + kt * KCHUNK + ch * 8;
        asm volatile("cp.async.cg.shared.global [%0], [%1], 16;" :: "r"(dst), "l"(src));
    }
    asm volatile("cp.async.commit_group;");
    asm volatile("cp.async.wait_group 0;" ::: "memory");
    __syncthreads();

    // warp w: rows w*32..w*32+31 (2 m-frags), all 32 cols (4 n8-frags)
    float acc[2][4][4];
#pragma unroll
    for (int i = 0; i < 2; i++)
#pragma unroll
        for (int j = 0; j < 4; j++)
#pragma unroll
            for (int k = 0; k < 4; k++) acc[i][j][k] = 0.0f;

    const int aRow = warp * 32 + ((lane >> 3) & 1) * 8 + (lane & 7);
    const int bRow = ((lane >> 3) & 1) * 8 + (lane & 7);
    const uint32_t colSel = ((lane >> 4) & 1) * 16;
    const uint32_t xorv = ((uint32_t)lane & 7u) << 4;

#pragma unroll
    for (int kt = 0; kt < 2; kt++) {
        const uint32_t bA = sA + kt * 16384;
        const uint32_t bB = sB + kt * 4096;
#pragma unroll
        for (int ks = 0; ks < 4; ks++) {
            uint32_t a[2][4], bb[2][4];
            const uint32_t cb = ((uint32_t)(ks * 32) + colSel) ^ xorv;
#pragma unroll
            for (int mf = 0; mf < 2; mf++) {
                uint32_t ad = bA + (uint32_t)(aRow + mf * 16) * 128 + cb;
                LDSM4(a[mf][0], a[mf][1], a[mf][2], a[mf][3], ad);
            }
#pragma unroll
            for (int ng = 0; ng < 2; ng++) {
                uint32_t bd = bB + (uint32_t)(bRow + ng * 16) * 128 + cb;
                LDSM4(bb[ng][0], bb[ng][1], bb[ng][2], bb[ng][3], bd);
            }
#pragma unroll
            for (int mf = 0; mf < 2; mf++)
#pragma unroll
                for (int nf = 0; nf < 4; nf++) {
                    const int ng = nf >> 1, lo = nf & 1;
                    MMA_F16(acc[mf][nf], a[mf], bb[ng][lo], bb[ng][2 + lo]);
                }
        }
    }

    // epilogue: fp16 into g_w2h[b][c][h*32 + n]
    __half* dst = g_w2h + (size_t)b * DIM * PKDIM + h * NA;
#pragma unroll
    for (int mf = 0; mf < 2; mf++) {
        const int r0 = mt * 128 + warp * 32 + mf * 16 + (lane >> 2);
        const int r8 = r0 + 8;
#pragma unroll
        for (int nf = 0; nf < 4; nf++) {
            const int c = nf * 8 + (lane & 3) * 2;
            *(__half2*)(dst + (size_t)r0 * PKDIM + c) = __floats2half2_rn(acc[mf][nf][0], acc[mf][nf][1]);
            *(__half2*)(dst + (size_t)r8 * PKDIM + c) = __floats2half2_rn(acc[mf][nf][2], acc[mf][nf][3]);
        }
    }
}

// ---------------- launch (single stream) ----------------
extern "C" void kernel_launch(void* const* d_in, const int* in_sizes, int n_in,
                              void* d_out, int out_size)
{
    const float* x    = (const float*)d_in[0];
    const float* ehs  = (const float*)d_in[1];
    const float* amap = (const float*)d_in[2];
    const float* q_w  = (const float*)d_in[3];
    const float* q_b  = (const float*)d_in[4];
    const float* kv_w = (const float*)d_in[5];
    const float* kv_b = (const float*)d_in[6];
    const float* p_w  = (const float*)d_in[7];
    const float* p_b  = (const float*)d_in[8];
    float* out = (float*)d_out;

    __half *xh, *qh, *qwh, *pwh, *ehsh, *kvwh, *probsh, *w2h;
    float *kv;
    cudaGetSymbolAddress((void**)&xh,     g_xh);
    cudaGetSymbolAddress((void**)&qh,     g_qh);
    cudaGetSymbolAddress((void**)&qwh,    g_qwh);
    cudaGetSymbolAddress((void**)&pwh,    g_pwh);
    cudaGetSymbolAddress((void**)&ehsh,   g_ehsh);
    cudaGetSymbolAddress((void**)&kvwh,   g_kvwh);
    cudaGetSymbolAddress((void**)&probsh, g_probsh);
    cudaGetSymbolAddress((void**)&w2h,    g_w2h);
    cudaGetSymbolAddress((void**)&kv,     g_kv);

    cudaFuncSetAttribute((const void*)gemm_f16_big<true>,
                         cudaFuncAttributeMaxDynamicSharedMemorySize, SM_TOT);
    cudaFuncSetAttribute((const void*)gemm_f16_small,
                         cudaFuncAttributeMaxDynamicSharedMemorySize, SSM_TOT);

    // routing positions
    minmax_kernel<<<1, 512>>>(amap);
    pos_kernel<<<(N_TOK + 255) / 256, 256>>>(amap);

    // fp16 conversions
    cvt_half_kernel<<<(N_TOK * DIM / 4 + 255) / 256, 256>>>(x, xh, N_TOK * DIM / 4);
    cvt_half_kernel<<<(DIM * DIM / 4 + 255) / 256, 256>>>(q_w, qwh, DIM * DIM / 4);
    cvt_half_kernel<<<(DIM * DIM / 4 + 255) / 256, 256>>>(p_w, pwh, DIM * DIM / 4);
    cvt_half_kernel<<<(KV_ROWS * ENC / 4 + 255) / 256, 256>>>(ehs, ehsh, KV_ROWS * ENC / 4);
    cvt_half_kernel<<<(2 * DIM * ENC / 4 + 255) / 256, 256>>>(kv_w, kvwh, 2 * DIM * ENC / 4);

    // q = RoPE(x @ q_w^T + q_b) -> fp16
    gemm_f16_big<true><<<dim3(DIM / 256, (N_TOK + 127) / 128), 256, SM_TOT>>>(
        xh, qwh, q_b, qh, N_TOK, DIM, DIM);

    // kv = ehs @ kv_w^T + kv_b -> fp32
    gemm_f16_small<<<dim3((2 * DIM) / 128, (KV_ROWS + 127) / 128, 1), 256, SSM_TOT>>>(
        ehsh, kvwh, kv_b, kv, KV_ROWS, 2 * DIM, ENC, 0, 0, 0);

    // split + RoPE(k); v -> fp16
    rope_k_split_kernel<<<(KV_ROWS * (DIM / 2) + 255) / 256, 256>>>();

    // attention probabilities
    attn_probs_kernel<<<dim3(NHEADS, N_T, 4), 256>>>();

    // W2 = V @ proj (tensor cores, per frame/head/c-tile) -> fp16
    w2_mma_kernel<<<dim3(DIM / 128, NHEADS, N_T), 128>>>();

    // out[b] = probs[b] @ W2[b]^T + p_b   (batched, K=384)
    gemm_f16_small<<<dim3(DIM / 128, (S_SP + 127) / 128, N_T), 256, SSM_TOT>>>(
        probsh, w2h, p_b, out, S_SP, DIM, PKDIM,
        (size_t)S_SP * PKDIM, (size_t)DIM * PKDIM, (size_t)S_SP * DIM);
}

// round 12
// speedup vs baseline: 1.9425x; 1.0541x over previous
#include <cuda_runtime.h>
#include <cuda_fp16.h>
#include <cstdint>
#include <math.h>

// ---------------- fixed problem shapes ----------------
#define N_TOK   32760          // 21 * 1560
#define DIM     1536
#define NHEADS  12
#define HD      128
#define S_SP    1560
#define N_T     21
#define ENC     768
#define NA      32
#define KV_ROWS 672
#define PKDIM   384            // NHEADS * NA
#define LOG2_10000 13.287712379549449f

// ---------------- scratch ----------------
__device__ __half g_xh[N_TOK * DIM];          // fp16 x
__device__ __half g_qh[N_TOK * DIM];          // fp16 RoPE'd q
__device__ __half g_qwh[DIM * DIM];           // fp16 q_w
__device__ __half g_pwh[DIM * DIM];           // fp16 proj_w
__device__ __half g_ehsh[KV_ROWS * ENC];      // fp16 encoder states
__device__ __half g_kvwh[2 * DIM * ENC];      // fp16 kv_w
__device__ float  g_kv[KV_ROWS * 2 * DIM];    // kv projection (fp32)
__device__ float  g_k[KV_ROWS * DIM];         // RoPE'd k (fp32)
__device__ __half g_vh[KV_ROWS * DIM];        // v (fp16, consumed by W2 fold)
__device__ __half g_probsh[N_TOK * PKDIM];    // softmax probs [t*S+s][h*32+a]
__device__ __half g_w2h[N_T * DIM * PKDIM];   // W2^T [b][c][h*32+a]
__device__ float  g_pos[N_TOK];
__device__ float  g_mm[4];

// ---------------- helpers ----------------
__device__ __forceinline__ uint32_t smem_u32(const void* p) {
    uint32_t r;
    asm("{.reg .u64 t; cvta.to.shared.u64 t, %1; cvt.u32.u64 %0, t;}" : "=r"(r) : "l"(p));
    return r;
}

#define LDSM4(r0, r1, r2, r3, addr)                                            \
    asm volatile("ldmatrix.sync.aligned.m8n8.x4.shared.b16 {%0,%1,%2,%3}, [%4];" \
                 : "=r"(r0), "=r"(r1), "=r"(r2), "=r"(r3) : "r"(addr))

#define MMA_F16(d, a, b0, b1)                                                  \
    asm volatile("mma.sync.aligned.m16n8k16.row.col.f32.f16.f16.f32 "           \
                 "{%0,%1,%2,%3},{%4,%5,%6,%7},{%8,%9},{%0,%1,%2,%3};"          \
                 : "+f"(d[0]), "+f"(d[1]), "+f"(d[2]), "+f"(d[3])              \
                 : "r"(a[0]), "r"(a[1]), "r"(a[2]), "r"(a[3]), "r"(b0), "r"(b1))

// ---------------- fp32 -> fp16 conversion ----------------
__global__ void cvt_half_kernel(const float* __restrict__ in, __half* __restrict__ out, int n4) {
    int i = blockIdx.x * blockDim.x + threadIdx.x;
    if (i >= n4) return;
    float4 v = ((const float4*)in)[i];
    __half2 h0 = __floats2half2_rn(v.x, v.y);
    __half2 h1 = __floats2half2_rn(v.z, v.w);
    uint2 pk;
    pk.x = *(uint32_t*)&h0;
    pk.y = *(uint32_t*)&h1;
    ((uint2*)out)[i] = pk;
}

// ---------------- min/max of attn-map rows (single CTA, float4) ----------------
__global__ void minmax_kernel(const float* __restrict__ m) {
    __shared__ float s0[512], s1[512], s2[512], s3[512];
    int tid = threadIdx.x;
    float mn0 = 1e30f, mx0 = -1e30f, mn1 = 1e30f, mx1 = -1e30f;
    const float4* m0v = (const float4*)m;
    const float4* m1v = (const float4*)(m + N_TOK);
    for (int i = tid; i < N_TOK / 4; i += 512) {
        float4 v0 = m0v[i], v1 = m1v[i];
        mn0 = fminf(mn0, fminf(fminf(v0.x, v0.y), fminf(v0.z, v0.w)));
        mx0 = fmaxf(mx0, fmaxf(fmaxf(v0.x, v0.y), fmaxf(v0.z, v0.w)));
        mn1 = fminf(mn1, fminf(fminf(v1.x, v1.y), fminf(v1.z, v1.w)));
        mx1 = fmaxf(mx1, fmaxf(fmaxf(v1.x, v1.y), fmaxf(v1.z, v1.w)));
    }
    s0[tid] = mn0; s1[tid] = mx0; s2[tid] = mn1; s3[tid] = mx1;
    __syncthreads();
    for (int off = 256; off > 0; off >>= 1) {
        if (tid < off) {
            s0[tid] = fminf(s0[tid], s0[tid + off]);
            s1[tid] = fmaxf(s1[tid], s1[tid + off]);
            s2[tid] = fminf(s2[tid], s2[tid + off]);
            s3[tid] = fmaxf(s3[tid], s3[tid + off]);
        }
        __syncthreads();
    }
    if (tid == 0) { g_mm[0] = s0[0]; g_mm[1] = s1[0]; g_mm[2] = s2[0]; g_mm[3] = s3[0]; }
}

// ---------------- routing positions ----------------
__global__ void pos_kernel(const float* __restrict__ m) {
    int n = blockIdx.x * blockDim.x + threadIdx.x;
    if (n >= N_TOK) return;
    float m0 = m[n], m1 = m[N_TOK + n];
    float r;
    if (m0 >= m1) r = (m0 - g_mm[0]) / (g_mm[1] - g_mm[0] + 1e-8f) * 4.0f;
    else          r = (m1 - g_mm[2]) / (g_mm[3] - g_mm[2] + 1e-8f) * 4.0f + 20.0f;
    g_pos[n] = r;
}

// ======== fp16 GEMM: CTA 128x128, 3-stage, occ 2 (all GEMMs) ========
#define KCHUNK  64
#define SSTAGES 3
#define SSM_SZ  16384
#define SSM_TOT (SSTAGES * 2 * SSM_SZ)          // 98304

__device__ __forceinline__ void fill_stage_s(
    const __half* __restrict__ A, const __half* __restrict__ B, int M, int K,
    int row0, int col0, int kt, uint32_t sA, uint32_t sB, int tid)
{
#pragma unroll
    for (int g = 0; g < 4; g++) {
        int ga = tid + g * 256;
        int row = ga >> 3, ch = ga & 7;
        uint32_t dst = sA + (uint32_t)row * 128u + (((uint32_t)ch * 16u) ^ (((uint32_t)row & 7u) << 4));
        const __half* src = A + (size_t)(row0 + row) * K + kt * KCHUNK + ch * 8;
        int sz = (row0 + row < M) ? 16 : 0;
        asm volatile("cp.async.cg.shared.global [%0], [%1], 16, %2;" :: "r"(dst), "l"(src), "r"(sz));
    }
#pragma unroll
    for (int g = 0; g < 4; g++) {
        int gb = tid + g * 256;
        int row = gb >> 3, ch = gb & 7;
        uint32_t dst = sB + (uint32_t)row * 128u + (((uint32_t)ch * 16u) ^ (((uint32_t)row & 7u) << 4));
        const __half* src = B + (size_t)(col0 + row) * K + kt * KCHUNK + ch * 8;
        asm volatile("cp.async.cg.shared.global [%0], [%1], 16;" :: "r"(dst), "l"(src));
    }
    asm volatile("cp.async.commit_group;");
}

template <bool FUSE_ROPE, bool HALF_OUT>
__global__ void __launch_bounds__(256, 2) gemm_f16_small(
    const __half* __restrict__ A, const __half* __restrict__ B,
    const float* __restrict__ bias, void* __restrict__ Cv,
    int M, int N, int K, size_t strA, size_t strB, size_t strC)
{
    extern __shared__ float smem[];
    const int tid  = threadIdx.x;
    const int lane = tid & 31, warp = tid >> 5;
    const int wm = warp >> 2, wn = warp & 3;      // 2x4 warp grid, warp tile 64x32
    const int row0 = blockIdx.y * 128, col0 = blockIdx.x * 128;

    A += (size_t)blockIdx.z * strA;
    B += (size_t)blockIdx.z * strB;

    const uint32_t sA = smem_u32(smem);
    const uint32_t sB = sA + SSTAGES * SSM_SZ;
    const int ktiles = K / KCHUNK;

    fill_stage_s(A, B, M, K, row0, col0, 0, sA, sB, tid);
    fill_stage_s(A, B, M, K, row0, col0, 1, sA + SSM_SZ, sB + SSM_SZ, tid);

    float acc[4][4][4];
#pragma unroll
    for (int i = 0; i < 4; i++)
#pragma unroll
        for (int j = 0; j < 4; j++)
#pragma unroll
            for (int k = 0; k < 4; k++) acc[i][j][k] = 0.0f;

    const int aRow = wm * 64 + ((lane >> 3) & 1) * 8 + (lane & 7);
    const int bRow = wn * 32 + ((lane >> 3) & 1) * 8 + (lane & 7);
    const uint32_t colSel = ((lane >> 4) & 1) * 16;
    const uint32_t xorv = ((uint32_t)lane & 7u) << 4;

    for (int it = 0; it < ktiles; it++) {
        if (it < ktiles - 1) asm volatile("cp.async.wait_group 1;" ::: "memory");
        else                 asm volatile("cp.async.wait_group 0;" ::: "memory");
        __syncthreads();
        const int st = it % 3;
        const uint32_t bA = sA + st * SSM_SZ;
        const uint32_t bB = sB + st * SSM_SZ;
#pragma unroll
        for (int ks = 0; ks < 4; ks++) {
            uint32_t a[4][4], bb[2][4];
            const uint32_t cb = ((uint32_t)(ks * 32) + colSel) ^ xorv;
#pragma unroll
            for (int mf = 0; mf < 4; mf++) {
                uint32_t ad = bA + (uint32_t)(aRow + mf * 16) * 128 + cb;
                LDSM4(a[mf][0], a[mf][1], a[mf][2], a[mf][3], ad);
            }
#pragma unroll
            for (int ng = 0; ng < 2; ng++) {
                uint32_t bd = bB + (uint32_t)(bRow + ng * 16) * 128 + cb;
                LDSM4(bb[ng][0], bb[ng][1], bb[ng][2], bb[ng][3], bd);
            }
#pragma unroll
            for (int mf = 0; mf < 4; mf++)
#pragma unroll
                for (int nf = 0; nf < 4; nf++) {
                    const int ng = nf >> 1, lo = nf & 1;
                    MMA_F16(acc[mf][nf], a[mf], bb[ng][lo], bb[ng][2 + lo]);
                }
        }
        if (it + 2 < ktiles) {
            const int r = it + 2;
            fill_stage_s(A, B, M, K, row0, col0, r,
                         sA + (r % 3) * SSM_SZ, sB + (r % 3) * SSM_SZ, tid);
        }
    }

    // epilogue: c0,c1 at (row=lane>>2, col=2*(lane&3)); c2,c3 at row+8
#pragma unroll
    for (int mf = 0; mf < 4; mf++) {
        const int r0 = row0 + wm * 64 + mf * 16 + (lane >> 2);
        const int r8 = r0 + 8;
        float pos0 = 0.f, pos8 = 0.f;
        if (FUSE_ROPE) {
            pos0 = g_pos[(r0 < M) ? r0 : 0];
            pos8 = g_pos[(r8 < M) ? r8 : 0];
        }
#pragma unroll
        for (int nf = 0; nf < 4; nf++) {
            const int c = col0 + wn * 32 + nf * 8 + (lane & 3) * 2;
            const float2 bv = *(const float2*)(bias + c);
            float o0 = acc[mf][nf][0] + bv.x;
            float o1 = acc[mf][nf][1] + bv.y;
            float o2 = acc[mf][nf][2] + bv.x;
            float o3 = acc[mf][nf][3] + bv.y;
            if (FUSE_ROPE) {
                const int i = (c & 127) >> 1;   // RoPE pair index within the 128-d head
                const float fr = exp2f(-(float)i * (LOG2_10000 / 64.0f));
                float sn, cs;
                sincosf(pos0 * fr, &sn, &cs);
                float t0 = o0 * cs - o1 * sn;
                o1 = o1 * cs + o0 * sn; o0 = t0;
                sincosf(pos8 * fr, &sn, &cs);
                float t2 = o2 * cs - o3 * sn;
                o3 = o3 * cs + o2 * sn; o2 = t2;
            }
            if (HALF_OUT) {
                __half* C = (__half*)Cv + (size_t)blockIdx.z * strC;
                if (r0 < M) *(__half2*)(C + (size_t)r0 * N + c) = __floats2half2_rn(o0, o1);
                if (r8 < M) *(__half2*)(C + (size_t)r8 * N + c) = __floats2half2_rn(o2, o3);
            } else {
                float* C = (float*)Cv + (size_t)blockIdx.z * strC;
                if (r0 < M) *(float2*)(C + (size_t)r0 * N + c) = make_float2(o0, o1);
                if (r8 < M) *(float2*)(C + (size_t)r8 * N + c) = make_float2(o2, o3);
            }
        }
    }
}

// ---------------- split kv -> k (RoPE, fp32) and v (fp16) ----------------
__global__ void rope_k_split_kernel() {
    int idx = blockIdx.x * blockDim.x + threadIdx.x;
    if (idx >= KV_ROWS * (DIM / 2)) return;
    int r = idx / (DIM / 2);
    int p = idx - r * (DIM / 2);
    int a = r & 31;
    float pos = (a < 16) ? 2.0f : 22.0f;
    int i = p & 63;
    float fr = exp2f(-(float)i * (LOG2_10000 / 64.0f));
    float th = pos * fr;
    float s, c;
    sincosf(th, &s, &c);
    const float* kvr = g_kv + (size_t)r * (2 * DIM);
    float ka = kvr[2 * p], kb = kvr[2 * p + 1];
    size_t o = (size_t)r * DIM + 2 * p;
    g_k[o]     = ka * c - kb * s;
    g_k[o + 1] = kb * c + ka * s;
    *(__half2*)(g_vh + o) = __floats2half2_rn(kvr[DIM + 2 * p], kvr[DIM + 2 * p + 1]);
}

// ---------------- attention probs (float-staged q; s-split 4-way) ----------
#define S_CHUNK 390
__global__ void __launch_bounds__(256) attn_probs_kernel() {
    const int h = blockIdx.x;
    const int t = blockIdx.y;
    const int chunk = blockIdx.z;
    __shared__ float ks[32][132];
    __shared__ float qs[8][128];

    const int tid = threadIdx.x;
    for (int i = tid; i < 32 * 128; i += 256) {
        int a = i >> 7, d = i & 127;
        ks[a][d] = g_k[(size_t)(t * 32 + a) * DIM + h * HD + d];
    }
    __syncthreads();

    const int w = tid >> 5, l = tid & 31;
    const int sBeg = chunk * S_CHUNK;
    const int sEnd = (sBeg + S_CHUNK < S_SP) ? sBeg + S_CHUNK : S_SP;

    for (int s = sBeg + w; s < sEnd; s += 8) {
        size_t qoff = (size_t)(t * S_SP + s) * DIM + h * HD;
        uint2 qp = *(const uint2*)(g_qh + qoff + 4 * l);
        float2 f0 = __half22float2(*(__half2*)&qp.x);
        float2 f1 = __half22float2(*(__half2*)&qp.y);
        *(float4*)&qs[w][4 * l] = make_float4(f0.x, f0.y, f1.x, f1.y);
        __syncwarp();

        float acc = 0.0f;
        const float4* qr = (const float4*)&qs[w][0];
        const float4* kr = (const float4*)&ks[l][0];
#pragma unroll
        for (int j = 0; j < 32; j++) {
            float4 a4 = qr[j];
            float4 b4 = kr[j];
            acc += a4.x * b4.x + a4.y * b4.y + a4.z * b4.z + a4.w * b4.w;
        }
        acc *= 0.08838834764831845f;

        float mx = acc;
#pragma unroll
        for (int o = 16; o > 0; o >>= 1) mx = fmaxf(mx, __shfl_xor_sync(0xFFFFFFFFu, mx, o));
        float e = __expf(acc - mx);
        float sum = e;
#pragma unroll
        for (int o = 16; o > 0; o >>= 1) sum += __shfl_xor_sync(0xFFFFFFFFu, sum, o);
        float p = e / sum;

        g_probsh[(size_t)(t * S_SP + s) * PKDIM + h * NA + l] = __float2half_rn(p);
        __syncwarp();
    }
}

// ---------------- W2 fold on tensor cores ------------------------------------
__global__ void __launch_bounds__(128) w2_mma_kernel() {
    const int mt = blockIdx.x;
    const int h  = blockIdx.y;
    const int b  = blockIdx.z;
    __shared__ __align__(16) char smem[2 * 16384 + 2 * 4096];

    const int tid = threadIdx.x;
    const int lane = tid & 31, warp = tid >> 5;
    const uint32_t sA = smem_u32(smem);
    const uint32_t sB = sA + 2 * 16384;

#pragma unroll
    for (int g = 0; g < 16; g++) {
        int i = tid + g * 128;
        int kt = i >> 10, row = (i >> 3) & 127, ch = i & 7;
        uint32_t dst = sA + kt * 16384 + (uint32_t)row * 128u +
                       (((uint32_t)ch * 16u) ^ (((uint32_t)row & 7u) << 4));
        const __half* src = g_pwh + (size_t)(mt * 128 + row) * DIM + h * HD + kt * KCHUNK + ch * 8;
        asm volatile("cp.async.cg.shared.global [%0], [%1], 16;" :: "r"(dst), "l"(src));
    }
#pragma unroll
    for (int g = 0; g < 4; g++) {
        int i = tid + g * 128;
        int kt = i >> 8, row = (i >> 3) & 31, ch = i & 7;
        uint32_t dst = sB + kt * 4096 + (uint32_t)row * 128u +
                       (((uint32_t)ch * 16u) ^ (((uint32_t)row & 7u) << 4));
        const __half* src = g_vh + (size_t)(b * 32 + row) * DIM + h * HD + kt * KCHUNK + ch * 8;
        asm volatile("cp.async.cg.shared.global [%0], [%1], 16;" :: "r"(dst), "l"(src));
    }
    asm volatile("cp.async.commit_group;");
    asm volatile("cp.async.wait_group 0;" ::: "memory");
    __syncthreads();

    float acc[2][4][4];
#pragma unroll
    for (int i = 0; i < 2; i++)
#pragma unroll
        for (int j = 0; j < 4; j++)
#pragma unroll
            for (int k = 0; k < 4; k++) acc[i][j][k] = 0.0f;

    const int aRow = warp * 32 + ((lane >> 3) & 1) * 8 + (lane & 7);
    const int bRow = ((lane >> 3) & 1) * 8 + (lane & 7);
    const uint32_t colSel = ((lane >> 4) & 1) * 16;
    const uint32_t xorv = ((uint32_t)lane & 7u) << 4;

#pragma unroll
    for (int kt = 0; kt < 2; kt++) {
        const uint32_t bA = sA + kt * 16384;
        const uint32_t bB = sB + kt * 4096;
#pragma unroll
        for (int ks = 0; ks < 4; ks++) {
            uint32_t a[2][4], bb[2][4];
            const uint32_t cb = ((uint32_t)(ks * 32) + colSel) ^ xorv;
#pragma unroll
            for (int mf = 0; mf < 2; mf++) {
                uint32_t ad = bA + (uint32_t)(aRow + mf * 16) * 128 + cb;
                LDSM4(a[mf][0], a[mf][1], a[mf][2], a[mf][3], ad);
            }
#pragma unroll
            for (int ng = 0; ng < 2; ng++) {
                uint32_t bd = bB + (uint32_t)(bRow + ng * 16) * 128 + cb;
                LDSM4(bb[ng][0], bb[ng][1], bb[ng][2], bb[ng][3], bd);
            }
#pragma unroll
            for (int mf = 0; mf < 2; mf++)
#pragma unroll
                for (int nf = 0; nf < 4; nf++) {
                    const int ng = nf >> 1, lo = nf & 1;
                    MMA_F16(acc[mf][nf], a[mf], bb[ng][lo], bb[ng][2 + lo]);
                }
        }
    }

    __half* dst = g_w2h + (size_t)b * DIM * PKDIM + h * NA;
#pragma unroll
    for (int mf = 0; mf < 2; mf++) {
        const int r0 = mt * 128 + warp * 32 + mf * 16 + (lane >> 2);
        const int r8 = r0 + 8;
#pragma unroll
        for (int nf = 0; nf < 4; nf++) {
            const int c = nf * 8 + (lane & 3) * 2;
            *(__half2*)(dst + (size_t)r0 * PKDIM + c) = __floats2half2_rn(acc[mf][nf][0], acc[mf][nf][1]);
            *(__half2*)(dst + (size_t)r8 * PKDIM + c) = __floats2half2_rn(acc[mf][nf][2], acc[mf][nf][3]);
        }
    }
}

// ---------------- launch (single stream) ----------------
extern "C" void kernel_launch(void* const* d_in, const int* in_sizes, int n_in,
                              void* d_out, int out_size)
{
    const float* x    = (const float*)d_in[0];
    const float* ehs  = (const float*)d_in[1];
    const float* amap = (const float*)d_in[2];
    const float* q_w  = (const float*)d_in[3];
    const float* q_b  = (const float*)d_in[4];
    const float* kv_w = (const float*)d_in[5];
    const float* kv_b = (const float*)d_in[6];
    const float* p_w  = (const float*)d_in[7];
    const float* p_b  = (const float*)d_in[8];
    float* out = (float*)d_out;

    __half *xh, *qh, *qwh, *pwh, *ehsh, *kvwh, *probsh, *w2h;
    float *kv;
    cudaGetSymbolAddress((void**)&xh,     g_xh);
    cudaGetSymbolAddress((void**)&qh,     g_qh);
    cudaGetSymbolAddress((void**)&qwh,    g_qwh);
    cudaGetSymbolAddress((void**)&pwh,    g_pwh);
    cudaGetSymbolAddress((void**)&ehsh,   g_ehsh);
    cudaGetSymbolAddress((void**)&kvwh,   g_kvwh);
    cudaGetSymbolAddress((void**)&probsh, g_probsh);
    cudaGetSymbolAddress((void**)&w2h,    g_w2h);
    cudaGetSymbolAddress((void**)&kv,     g_kv);

    cudaFuncSetAttribute((const void*)gemm_f16_small<true, true>,
                         cudaFuncAttributeMaxDynamicSharedMemorySize, SSM_TOT);
    cudaFuncSetAttribute((const void*)gemm_f16_small<false, false>,
                         cudaFuncAttributeMaxDynamicSharedMemorySize, SSM_TOT);

    // routing positions
    minmax_kernel<<<1, 512>>>(amap);
    pos_kernel<<<(N_TOK + 255) / 256, 256>>>(amap);

    // fp16 conversions
    cvt_half_kernel<<<(N_TOK * DIM / 4 + 255) / 256, 256>>>(x, xh, N_TOK * DIM / 4);
    cvt_half_kernel<<<(DIM * DIM / 4 + 255) / 256, 256>>>(q_w, qwh, DIM * DIM / 4);
    cvt_half_kernel<<<(DIM * DIM / 4 + 255) / 256, 256>>>(p_w, pwh, DIM * DIM / 4);
    cvt_half_kernel<<<(KV_ROWS * ENC / 4 + 255) / 256, 256>>>(ehs, ehsh, KV_ROWS * ENC / 4);
    cvt_half_kernel<<<(2 * DIM * ENC / 4 + 255) / 256, 256>>>(kv_w, kvwh, 2 * DIM * ENC / 4);

    // q = RoPE(x @ q_w^T + q_b) -> fp16   (occ-2 128x128 config)
    gemm_f16_small<true, true><<<dim3(DIM / 128, (N_TOK + 127) / 128, 1), 256, SSM_TOT>>>(
        xh, qwh, q_b, qh, N_TOK, DIM, DIM, 0, 0, 0);

    // kv = ehs @ kv_w^T + kv_b -> fp32
    gemm_f16_small<false, false><<<dim3((2 * DIM) / 128, (KV_ROWS + 127) / 128, 1), 256, SSM_TOT>>>(
        ehsh, kvwh, kv_b, kv, KV_ROWS, 2 * DIM, ENC, 0, 0, 0);

    // split + RoPE(k); v -> fp16
    rope_k_split_kernel<<<(KV_ROWS * (DIM / 2) + 255) / 256, 256>>>();

    // attention probabilities
    attn_probs_kernel<<<dim3(NHEADS, N_T, 4), 256>>>();

    // W2 = V @ proj (tensor cores) -> fp16
    w2_mma_kernel<<<dim3(DIM / 128, NHEADS, N_T), 128>>>();

    // out[b] = probs[b] @ W2[b]^T + p_b   (batched, K=384)
    gemm_f16_small<false, false><<<dim3(DIM / 128, (S_SP + 127) / 128, N_T), 256, SSM_TOT>>>(
        probsh, w2h, p_b, out, S_SP, DIM, PKDIM,
        (size_t)S_SP * PKDIM, (size_t)DIM * PKDIM, (size_t)S_SP * DIM);
}